// round 11
// baseline (speedup 1.0000x reference)
#include <cuda_runtime.h>
#include <cuda_bf16.h>
#include <stdint.h>
#include <math.h>

#define BB   4
#define T    8192
#define DIM  512
#define H    8
#define D    64
#define C    64
#define NCH  128
#define BH   32
#define EPSR 1.1920929e-07f
#define MAXLR 0.01f
#define PH   72

// ------------------- scratch -------------------
__device__ float g_s   [BB*T*DIM];
__device__ float g_q   [BH*T*D];
__device__ float g_k   [BH*T*D];
__device__ float g_v   [BH*T*D];
__device__ float g_lr  [BH*T];
__device__ float g_gate[BH*T];
__device__ float g_mg  [BH*NCH];
__device__ float g_dec [BH*NCH];
__device__ uint32_t g_u1 [(long)BH*NCH*2048];   // bf16x2-packed surprises/updates
__device__ uint32_t g_u2 [(long)BH*NCH*2048];
__device__ float g_vals[BB*T*DIM];

__device__ __forceinline__ float sigm(float x){ return 1.f/(1.f+__expf(-x)); }

__device__ __forceinline__ uint32_t smem_u32(const void* p){
    uint32_t a;
    asm("{ .reg .u64 t; cvta.to.shared.u64 t, %1; cvt.u32.u64 %0, t; }" : "=r"(a) : "l"(p));
    return a;
}
__device__ __forceinline__ void ldm4(uint32_t* r, uint32_t addr){
    asm volatile("ldmatrix.sync.aligned.m8n8.x4.shared.b16 {%0,%1,%2,%3}, [%4];"
                 : "=r"(r[0]),"=r"(r[1]),"=r"(r[2]),"=r"(r[3]) : "r"(addr));
}
__device__ __forceinline__ void ldm4t(uint32_t* r, uint32_t addr){
    asm volatile("ldmatrix.sync.aligned.m8n8.x4.trans.shared.b16 {%0,%1,%2,%3}, [%4];"
                 : "=r"(r[0]),"=r"(r[1]),"=r"(r[2]),"=r"(r[3]) : "r"(addr));
}
__device__ __forceinline__ void mma16816(float* c, const uint32_t* a, uint32_t b0, uint32_t b1){
    asm volatile("mma.sync.aligned.m16n8k16.row.col.f32.bf16.bf16.f32 "
                 "{%0,%1,%2,%3}, {%4,%5,%6,%7}, {%8,%9}, {%0,%1,%2,%3};"
                 : "+f"(c[0]),"+f"(c[1]),"+f"(c[2]),"+f"(c[3])
                 : "r"(a[0]),"r"(a[1]),"r"(a[2]),"r"(a[3]), "r"(b0),"r"(b1));
}
__device__ __forceinline__ void bsplit(float v, uint16_t& hi, uint16_t& lo){
    __nv_bfloat16 h = __float2bfloat16(v);
    __nv_bfloat16 l = __float2bfloat16(v - __bfloat162float(h));
    hi = __bfloat16_as_ushort(h);
    lo = __bfloat16_as_ushort(l);
}
__device__ __forceinline__ float bjoin(uint16_t hi, uint16_t lo){
    return __bfloat162float(__ushort_as_bfloat16(hi)) +
           __bfloat162float(__ushort_as_bfloat16(lo));
}
__device__ __forceinline__ void bsplit2(float v0, float v1, uint32_t& hw, uint32_t& lw){
    uint16_t h0,l0,h1,l1;
    bsplit(v0,h0,l0); bsplit(v1,h1,l1);
    hw = (uint32_t)h0 | ((uint32_t)h1<<16);
    lw = (uint32_t)l0 | ((uint32_t)l1<<16);
}
__device__ __forceinline__ uint32_t bpack2(float v0, float v1){
    return (uint32_t)__bfloat16_as_ushort(__float2bfloat16(v0))
         | ((uint32_t)__bfloat16_as_ushort(__float2bfloat16(v1))<<16);
}
__device__ __forceinline__ float2 bunpack2(uint32_t w){
    return make_float2(__bfloat162float(__ushort_as_bfloat16((uint16_t)(w & 0xffff))),
                       __bfloat162float(__ushort_as_bfloat16((uint16_t)(w >> 16))));
}

// ===== 8-warp 64x64x64 split GEMM (m16 x n32), 3-term =====
template<int AT, int BT, class CB>
__device__ __forceinline__ void tmm64(int wid, int l,
    const uint16_t* Ah_, const uint16_t* Al_,
    const uint16_t* Bh_, const uint16_t* Bl_, CB cb)
{
    int wm = wid & 3, wn = wid >> 2;
    float acc[4][4];
    #pragma unroll
    for (int i = 0; i < 4; i++)
        #pragma unroll
        for (int e = 0; e < 4; e++) acc[i][e] = 0.f;
    uint32_t aAh = smem_u32(Ah_), aAl = smem_u32(Al_);
    uint32_t aBh = smem_u32(Bh_), aBl = smem_u32(Bl_);
    #pragma unroll
    for (int ks = 0; ks < 4; ks++){
        int k0 = ks*16;
        uint32_t ah[4], al[4];
        if (!AT){
            uint32_t ad = (uint32_t)((wm*16 + (l&15))*PH + k0 + ((l>>4)<<3))*2u;
            ldm4(ah, aAh + ad); ldm4(al, aAl + ad);
        } else {
            uint32_t ad = (uint32_t)((k0 + (l&15))*PH + wm*16 + ((l>>4)<<3))*2u;
            uint32_t t[4];
            ldm4t(t, aAh + ad); ah[0]=t[0]; ah[1]=t[2]; ah[2]=t[1]; ah[3]=t[3];
            ldm4t(t, aAl + ad); al[0]=t[0]; al[1]=t[2]; al[2]=t[1]; al[3]=t[3];
        }
        uint32_t bh[2][4], bl[2][4];
        #pragma unroll
        for (int hh = 0; hh < 2; hh++){
            int n0 = wn*32 + hh*16;
            if (!BT){
                uint32_t bd = (uint32_t)((k0 + (l&15))*PH + n0 + ((l>>4)<<3))*2u;
                ldm4t(bh[hh], aBh + bd); ldm4t(bl[hh], aBl + bd);
            } else {
                uint32_t bd = (uint32_t)((n0 + (l&15))*PH + k0 + ((l>>4)<<3))*2u;
                uint32_t t[4];
                ldm4(t, aBh + bd); bh[hh][0]=t[0]; bh[hh][1]=t[2]; bh[hh][2]=t[1]; bh[hh][3]=t[3];
                ldm4(t, aBl + bd); bl[hh][0]=t[0]; bl[hh][1]=t[2]; bl[hh][2]=t[1]; bl[hh][3]=t[3];
            }
        }
        #pragma unroll
        for (int nt = 0; nt < 4; nt++){
            int hh = nt>>1, o = (nt&1)*2;
            mma16816(acc[nt], ah, bh[hh][o], bh[hh][o+1]);
            mma16816(acc[nt], al, bh[hh][o], bh[hh][o+1]);
            mma16816(acc[nt], ah, bl[hh][o], bl[hh][o+1]);
        }
    }
    int m0 = wm*16 + (l>>2);
    #pragma unroll
    for (int nt = 0; nt < 4; nt++){
        int n = wn*32 + nt*8 + ((l&3)<<1);
        cb(m0,   n, acc[nt][0], acc[nt][1]);
        cb(m0+8, n, acc[nt][2], acc[nt][3]);
    }
}

// ===== 16-warp variant (m16 x n16), 3-term =====
template<int AT, int BT, class CB>
__device__ __forceinline__ void tmm64w(int wid, int l,
    const uint16_t* Ah_, const uint16_t* Al_,
    const uint16_t* Bh_, const uint16_t* Bl_, CB cb)
{
    int wm = wid & 3, wn = wid >> 2;
    float acc[2][4];
    #pragma unroll
    for (int i = 0; i < 2; i++)
        #pragma unroll
        for (int e = 0; e < 4; e++) acc[i][e] = 0.f;
    uint32_t aAh = smem_u32(Ah_), aAl = smem_u32(Al_);
    uint32_t aBh = smem_u32(Bh_), aBl = smem_u32(Bl_);
    #pragma unroll
    for (int ks = 0; ks < 4; ks++){
        int k0 = ks*16;
        uint32_t ah[4], al[4];
        if (!AT){
            uint32_t ad = (uint32_t)((wm*16 + (l&15))*PH + k0 + ((l>>4)<<3))*2u;
            ldm4(ah, aAh + ad); ldm4(al, aAl + ad);
        } else {
            uint32_t ad = (uint32_t)((k0 + (l&15))*PH + wm*16 + ((l>>4)<<3))*2u;
            uint32_t t[4];
            ldm4t(t, aAh + ad); ah[0]=t[0]; ah[1]=t[2]; ah[2]=t[1]; ah[3]=t[3];
            ldm4t(t, aAl + ad); al[0]=t[0]; al[1]=t[2]; al[2]=t[1]; al[3]=t[3];
        }
        int n0 = wn*16;
        uint32_t bh[4], bl[4];
        if (!BT){
            uint32_t bd = (uint32_t)((k0 + (l&15))*PH + n0 + ((l>>4)<<3))*2u;
            ldm4t(bh, aBh + bd); ldm4t(bl, aBl + bd);
        } else {
            uint32_t bd = (uint32_t)((n0 + (l&15))*PH + k0 + ((l>>4)<<3))*2u;
            uint32_t t[4];
            ldm4(t, aBh + bd); bh[0]=t[0]; bh[1]=t[2]; bh[2]=t[1]; bh[3]=t[3];
            ldm4(t, aBl + bd); bl[0]=t[0]; bl[1]=t[2]; bl[2]=t[1]; bl[3]=t[3];
        }
        #pragma unroll
        for (int q = 0; q < 2; q++){
            int o = q*2;
            mma16816(acc[q], ah, bh[o], bh[o+1]);
            mma16816(acc[q], al, bh[o], bh[o+1]);
            mma16816(acc[q], ah, bl[o], bl[o+1]);
        }
    }
    int m0 = wm*16 + (l>>2);
    #pragma unroll
    for (int q = 0; q < 2; q++){
        int n = wn*16 + q*8 + ((l&3)<<1);
        cb(m0,   n, acc[q][0], acc[q][1]);
        cb(m0+8, n, acc[q][2], acc[q][3]);
    }
}

// ===== single-term variants (gradient path) =====
template<int AT, int BT, class CB>
__device__ __forceinline__ void tmm64_1(int wid, int l,
    const uint16_t* Ah_, const uint16_t* Bh_, CB cb)
{
    int wm = wid & 3, wn = wid >> 2;
    float acc[4][4];
    #pragma unroll
    for (int i = 0; i < 4; i++)
        #pragma unroll
        for (int e = 0; e < 4; e++) acc[i][e] = 0.f;
    uint32_t aAh = smem_u32(Ah_), aBh = smem_u32(Bh_);
    #pragma unroll
    for (int ks = 0; ks < 4; ks++){
        int k0 = ks*16;
        uint32_t ah[4];
        if (!AT){
            uint32_t ad = (uint32_t)((wm*16 + (l&15))*PH + k0 + ((l>>4)<<3))*2u;
            ldm4(ah, aAh + ad);
        } else {
            uint32_t ad = (uint32_t)((k0 + (l&15))*PH + wm*16 + ((l>>4)<<3))*2u;
            uint32_t t[4];
            ldm4t(t, aAh + ad); ah[0]=t[0]; ah[1]=t[2]; ah[2]=t[1]; ah[3]=t[3];
        }
        #pragma unroll
        for (int hh = 0; hh < 2; hh++){
            int n0 = wn*32 + hh*16;
            uint32_t bh[4];
            if (!BT){
                uint32_t bd = (uint32_t)((k0 + (l&15))*PH + n0 + ((l>>4)<<3))*2u;
                ldm4t(bh, aBh + bd);
            } else {
                uint32_t bd = (uint32_t)((n0 + (l&15))*PH + k0 + ((l>>4)<<3))*2u;
                uint32_t t[4];
                ldm4(t, aBh + bd); bh[0]=t[0]; bh[1]=t[2]; bh[2]=t[1]; bh[3]=t[3];
            }
            mma16816(acc[hh*2],   ah, bh[0], bh[1]);
            mma16816(acc[hh*2+1], ah, bh[2], bh[3]);
        }
    }
    int m0 = wm*16 + (l>>2);
    #pragma unroll
    for (int nt = 0; nt < 4; nt++){
        int n = wn*32 + nt*8 + ((l&3)<<1);
        cb(m0,   n, acc[nt][0], acc[nt][1]);
        cb(m0+8, n, acc[nt][2], acc[nt][3]);
    }
}
template<int AT, int BT, class CB>
__device__ __forceinline__ void tmm64w1(int wid, int l,
    const uint16_t* Ah_, const uint16_t* Bh_, CB cb)
{
    int wm = wid & 3, wn = wid >> 2;
    float acc[2][4];
    #pragma unroll
    for (int i = 0; i < 2; i++)
        #pragma unroll
        for (int e = 0; e < 4; e++) acc[i][e] = 0.f;
    uint32_t aAh = smem_u32(Ah_), aBh = smem_u32(Bh_);
    #pragma unroll
    for (int ks = 0; ks < 4; ks++){
        int k0 = ks*16;
        uint32_t ah[4];
        if (!AT){
            uint32_t ad = (uint32_t)((wm*16 + (l&15))*PH + k0 + ((l>>4)<<3))*2u;
            ldm4(ah, aAh + ad);
        } else {
            uint32_t ad = (uint32_t)((k0 + (l&15))*PH + wm*16 + ((l>>4)<<3))*2u;
            uint32_t t[4];
            ldm4t(t, aAh + ad); ah[0]=t[0]; ah[1]=t[2]; ah[2]=t[1]; ah[3]=t[3];
        }
        int n0 = wn*16;
        uint32_t bh[4];
        if (!BT){
            uint32_t bd = (uint32_t)((k0 + (l&15))*PH + n0 + ((l>>4)<<3))*2u;
            ldm4t(bh, aBh + bd);
        } else {
            uint32_t bd = (uint32_t)((n0 + (l&15))*PH + k0 + ((l>>4)<<3))*2u;
            uint32_t t[4];
            ldm4(t, aBh + bd); bh[0]=t[0]; bh[1]=t[2]; bh[2]=t[1]; bh[3]=t[3];
        }
        mma16816(acc[0], ah, bh[0], bh[1]);
        mma16816(acc[1], ah, bh[2], bh[3]);
    }
    int m0 = wm*16 + (l>>2);
    #pragma unroll
    for (int q = 0; q < 2; q++){
        int n = wn*16 + q*8 + ((l&3)<<1);
        cb(m0,   n, acc[q][0], acc[q][1]);
        cb(m0+8, n, acc[q][2], acc[q][3]);
    }
}

// ------------------- K1 -------------------
__global__ void k1_rmsnorm(const float* __restrict__ seq,
                           const float* __restrict__ Wstep,
                           const float* __restrict__ Wgate)
{
    int tok = blockIdx.x;
    int tid = threadIdx.x;
    __shared__ float s[DIM];
    __shared__ float red[256];
    float x0 = seq[(long)tok*DIM + tid*2];
    float x1 = seq[(long)tok*DIM + tid*2 + 1];
    red[tid] = x0*x0 + x1*x1;
    __syncthreads();
    for (int o = 128; o > 0; o >>= 1){
        if (tid < o) red[tid] += red[tid+o];
        __syncthreads();
    }
    float sc = rsqrtf(red[0]*(1.f/DIM) + EPSR);
    float s0 = x0*sc, s1 = x1*sc;
    s[tid*2] = s0; s[tid*2+1] = s1;
    g_s[(long)tok*DIM + tid*2]     = s0;
    g_s[(long)tok*DIM + tid*2 + 1] = s1;
    __syncthreads();
    int w = tid >> 5, lane = tid & 31;
    float ds = 0.f, dg = 0.f;
    for (int i = lane; i < DIM; i += 32){
        float sv = s[i];
        ds += sv * Wstep[i*H + w];
        dg += sv * Wgate[i*H + w];
    }
    for (int o = 16; o; o >>= 1){
        ds += __shfl_down_sync(0xffffffffu, ds, o);
        dg += __shfl_down_sync(0xffffffffu, dg, o);
    }
    if (lane == 0){
        int b = tok / T, t = tok % T;
        int bh = b*H + w;
        g_lr  [(long)bh*T + t] = sigm(ds) * MAXLR * (2.0f/D);
        g_gate[(long)bh*T + t] = sigm(dg);
    }
}

// ------------------- K2 -------------------
__global__ void k2_chunkgates(const float* __restrict__ Wmom,
                              const float* __restrict__ Wdecay)
{
    int nc = blockIdx.x, b = blockIdx.y;
    int tid = threadIdx.x;
    __shared__ float m[DIM];
    const float* base = g_s + ((long)b*T + nc*C)*DIM;
    float a0 = 0.f, a1 = 0.f;
    for (int r = 0; r < C; r++){
        a0 += base[(long)r*DIM + tid*2];
        a1 += base[(long)r*DIM + tid*2 + 1];
    }
    m[tid*2] = a0*(1.f/C); m[tid*2+1] = a1*(1.f/C);
    __syncthreads();
    int w = tid >> 5, lane = tid & 31;
    float dm = 0.f, dd = 0.f;
    for (int i = lane; i < DIM; i += 32){
        float v = m[i];
        dm += v * Wmom[i*H + w];
        dd += v * Wdecay[i*H + w];
    }
    for (int o = 16; o; o >>= 1){
        dm += __shfl_down_sync(0xffffffffu, dm, o);
        dd += __shfl_down_sync(0xffffffffu, dd, o);
    }
    if (lane == 0){
        int bh = b*H + w;
        g_mg [bh*NCH + nc] = sigm(dm);
        g_dec[bh*NCH + nc] = sigm(dd);
    }
}

// ===================== big GEMMs: bf16 2-split, 512 threads, 2-stage buffer =====================
#define PA 40
#define PB 136
#define STGH (128*PA + 128*PA + 32*PB + 32*PB)
__global__ void __launch_bounds__(512, 2)
kmma(const float* __restrict__ W0, const float* __restrict__ W1,
     float* __restrict__ outp, int mode)
{
    extern __shared__ __align__(16) uint16_t kms[];

    int tid = threadIdx.x, wid = tid >> 5, l = tid & 31;
    int wm = wid & 3, wn = wid >> 2;       // warp tile m32 x n32
    int row0 = blockIdx.y * 128;
    int col0 = blockIdx.x * 128;

    const float* A; const float* Bp; int ldb, bc0;
    if (mode == 0){
        A = g_s;
        if (col0 < 512){ Bp = W0; ldb = 512;  bc0 = col0; }
        else           { Bp = W1; ldb = 1024; bc0 = col0 - 512; }
    } else {
        A = g_vals; Bp = W0; ldb = 512; bc0 = col0;
    }

    float acc[2][4][4];
    #pragma unroll
    for (int i = 0; i < 2; i++)
        #pragma unroll
        for (int j = 0; j < 4; j++)
            #pragma unroll
            for (int e = 0; e < 4; e++) acc[i][j][e] = 0.f;

    int a_row = tid >> 2, a_cg = (tid & 3)*8;    // 128 rows x 32 cols, 8 floats/thread
    int b_row = tid >> 4, b_cg = (tid & 15)*8;   // 32 rows x 128 cols, 8 floats/thread

    uint32_t base0 = smem_u32(kms);
    auto AhP = [&](int s){ return kms + s*STGH; };
    auto AlP = [&](int s){ return kms + s*STGH + 128*PA; };
    auto BhP = [&](int s){ return kms + s*STGH + 2*128*PA; };
    auto BlP = [&](int s){ return kms + s*STGH + 2*128*PA + 32*PB; };

    float aR[8];
    {
        const float* ap = A + (long)(row0 + a_row)*512 + a_cg;
        *(float4*)(aR)   = *(const float4*)(ap);
        *(float4*)(aR+4) = *(const float4*)(ap + 4);
        uint16_t* Ah = AhP(0); uint16_t* Al = AlP(0);
        #pragma unroll
        for (int j = 0; j < 2; j++){
            uint32_t hw0, lw0, hw1, lw1;
            bsplit2(aR[j*4+0], aR[j*4+1], hw0, lw0);
            bsplit2(aR[j*4+2], aR[j*4+3], hw1, lw1);
            int o = a_row*PA + a_cg + j*4;
            *(uint32_t*)&Ah[o]   = hw0; *(uint32_t*)&Ah[o+2] = hw1;
            *(uint32_t*)&Al[o]   = lw0; *(uint32_t*)&Al[o+2] = lw1;
        }
        const float* bp = Bp + (long)b_row*ldb + bc0 + b_cg;
        uint16_t* Bh = BhP(0); uint16_t* Bl = BlP(0);
        #pragma unroll
        for (int j = 0; j < 2; j++){
            float4 x = *(const float4*)(bp + j*4);
            uint32_t hw0, lw0, hw1, lw1;
            bsplit2(x.x, x.y, hw0, lw0);
            bsplit2(x.z, x.w, hw1, lw1);
            int o = b_row*PB + b_cg + j*4;
            *(uint32_t*)&Bh[o]   = hw0; *(uint32_t*)&Bh[o+2] = hw1;
            *(uint32_t*)&Bl[o]   = lw0; *(uint32_t*)&Bl[o+2] = lw1;
        }
    }
    __syncthreads();

    for (int i = 0; i < 16; i++){
        int cur = i & 1, nxt = cur ^ 1;
        if (i < 15){
            const float* ap = A + (long)(row0 + a_row)*512 + (i+1)*32 + a_cg;
            *(float4*)(aR)   = *(const float4*)(ap);
            *(float4*)(aR+4) = *(const float4*)(ap + 4);
        }

        uint32_t aAh = base0 + (uint32_t)(cur*STGH)*2u;
        uint32_t aAl = aAh + 128*PA*2u;
        uint32_t aBh = aAh + 2u*128*PA*2u;
        uint32_t aBl = aBh + 32*PB*2u;

        #pragma unroll
        for (int ks = 0; ks < 2; ks++){
            int k0 = ks*16;
            int arow = wm*32 + (l & 15);
            int acol = k0 + (l >> 4)*8;
            int brow = k0 + (l & 15);
            int bcol = wn*32 + (l >> 4)*8;

            uint32_t ah[2][4], al2[2][4], bh2[2][4], bl2[2][4];
            #pragma unroll
            for (int mt = 0; mt < 2; mt++){
                ldm4(ah[mt],  aAh + ((arow + mt*16)*PA + acol)*2);
                ldm4(al2[mt], aAl + ((arow + mt*16)*PA + acol)*2);
            }
            #pragma unroll
            for (int bt = 0; bt < 2; bt++){
                ldm4t(bh2[bt], aBh + (brow*PB + bcol + bt*16)*2);
                ldm4t(bl2[bt], aBl + (brow*PB + bcol + bt*16)*2);
            }
            #pragma unroll
            for (int mt = 0; mt < 2; mt++)
                #pragma unroll
                for (int nt = 0; nt < 4; nt++){
                    int hh = nt>>1, o = (nt&1)*2;
                    mma16816(acc[mt][nt], ah[mt],  bh2[hh][o], bh2[hh][o+1]);
                    mma16816(acc[mt][nt], al2[mt], bh2[hh][o], bh2[hh][o+1]);
                    mma16816(acc[mt][nt], ah[mt],  bl2[hh][o], bl2[hh][o+1]);
                }
        }

        if (i < 15){
            uint16_t* Ah = AhP(nxt); uint16_t* Al = AlP(nxt);
            #pragma unroll
            for (int j = 0; j < 2; j++){
                uint32_t hw0, lw0, hw1, lw1;
                bsplit2(aR[j*4+0], aR[j*4+1], hw0, lw0);
                bsplit2(aR[j*4+2], aR[j*4+3], hw1, lw1);
                int o = a_row*PA + a_cg + j*4;
                *(uint32_t*)&Ah[o]   = hw0; *(uint32_t*)&Ah[o+2] = hw1;
                *(uint32_t*)&Al[o]   = lw0; *(uint32_t*)&Al[o+2] = lw1;
            }
            const float* bp = Bp + (long)((i+1)*32 + b_row)*ldb + bc0 + b_cg;
            uint16_t* Bh = BhP(nxt); uint16_t* Bl = BlP(nxt);
            #pragma unroll
            for (int j = 0; j < 2; j++){
                float4 x = *(const float4*)(bp + j*4);
                uint32_t hw0, lw0, hw1, lw1;
                bsplit2(x.x, x.y, hw0, lw0);
                bsplit2(x.z, x.w, hw1, lw1);
                int o = b_row*PB + b_cg + j*4;
                *(uint32_t*)&Bh[o]   = hw0; *(uint32_t*)&Bh[o+2] = hw1;
                *(uint32_t*)&Bl[o]   = lw0; *(uint32_t*)&Bl[o+2] = lw1;
            }
        }
        __syncthreads();
    }

    int g = l >> 2, tq = l & 3;
    #pragma unroll
    for (int mt = 0; mt < 2; mt++){
        #pragma unroll
        for (int nt = 0; nt < 4; nt++){
            int col = col0 + wn*32 + nt*8 + 2*tq;
            #pragma unroll
            for (int half = 0; half < 2; half++){
                int r = row0 + wm*32 + mt*16 + g + half*8;
                float2 v = make_float2(acc[mt][nt][half*2], acc[mt][nt][half*2+1]);
                if (mode == 0){
                    int mtx = col >> 9, cc = col & 511;
                    int hh = cc >> 6, j0 = cc & 63;
                    float* dst = (mtx == 0) ? g_q : (mtx == 1 ? g_k : g_v);
                    int b_ = r >> 13, tok = r & 8191;
                    *(float2*)(dst + ((long)(b_*H + hh)*T + tok)*D + j0) = v;
                } else {
                    int b_ = r >> 13, jr = r & 8191;
                    if (jr <= T - C)
                        *(float2*)(outp + ((long)b_*T + jr + (C-1))*DIM + col) = v;
                }
            }
        }
    }
}

// ------------------- K4: per-chunk MLP grads (512 thr, 3 CTAs/SM) -------------------
__global__ void __launch_bounds__(512, 3)
k4_grads(const float* __restrict__ w1, const float* __restrict__ w2)
{
    extern __shared__ __align__(16) char smraw[];
    uint16_t* Kh = (uint16_t*)smraw;
    uint16_t* Kl = Kh + 64*PH;
    uint16_t* Wh = Kl + 64*PH;
    uint16_t* Wl = Wh + 64*PH;
    uint16_t* Hh = Wl + 64*PH;
    uint16_t* Hl = Hh + 64*PH;
    uint16_t* Yh = Hl + 64*PH;
    uint16_t* Dh = Yh + 64*PH;
    float* slr = (float*)(Dh + 64*PH);

    int nc = blockIdx.x, bh = blockIdx.y;
    int tid = threadIdx.x, wid = tid >> 5, l = tid & 31;
    long base = ((long)bh*T + nc*C)*D;
    for (int idx = tid; idx < 4096; idx += 512){
        int r = idx >> 6, c = idx & 63;
        uint16_t h_, l_;
        bsplit(g_k[base + idx], h_, l_); Kh[r*PH+c] = h_; Kl[r*PH+c] = l_;
        bsplit(w1[idx],        h_, l_); Wh[r*PH+c] = h_; Wl[r*PH+c] = l_;
    }
    if (tid < 64) slr[tid] = g_lr[(long)bh*T + nc*C + tid];
    __syncthreads();

    tmm64w<0,0>(wid, l, Kh, Kl, Wh, Wl, [&](int m, int n, float v0, float v1){
        *(uint32_t*)&Dh[m*PH+n] = bpack2(v0, v1);
        uint32_t hw, lw;
        bsplit2(v0*sigm(v0), v1*sigm(v1), hw, lw);
        *(uint32_t*)&Hh[m*PH+n] = hw; *(uint32_t*)&Hl[m*PH+n] = lw;
    });
    __syncthreads();
    for (int idx = tid; idx < 4096; idx += 512){
        int r = idx >> 6, c = idx & 63;
        uint16_t h_, l_; bsplit(w2[idx], h_, l_);
        Wh[r*PH+c] = h_; Wl[r*PH+c] = l_;
    }
    __syncthreads();
    tmm64w<0,0>(wid, l, Hh, Hl, Wh, Wl, [&](int m, int n, float y0, float y1){
        float2 vv = *(const float2*)&g_v[base + m*64 + n];
        float lr = slr[m];
        *(uint32_t*)&Yh[m*PH+n] = bpack2(lr*(y0 - vv.x), lr*(y1 - vv.y));
    });
    __syncthreads();
    long gbase = ((long)bh*NCH + nc)*2048;
    if (wid < 8){
        tmm64_1<1,0>(wid, l, Hh, Yh, [&](int m, int n, float v0, float v1){
            g_u2[gbase + m*32 + (n>>1)] = bpack2(-v0, -v1);
        });
    } else {
        tmm64_1<0,1>(wid-8, l, Yh, Wh, [&](int m, int n, float v0, float v1){
            float x0 = __bfloat162float(__ushort_as_bfloat16(Dh[m*PH+n]));
            float x1 = __bfloat162float(__ushort_as_bfloat16(Dh[m*PH+n+1]));
            float sg0 = sigm(x0), sg1 = sigm(x1);
            float dx0 = v0 * sg0 * (1.f + x0*(1.f - sg0));
            float dx1 = v1 * sg1 * (1.f + x1*(1.f - sg1));
            *(uint32_t*)&Dh[m*PH+n] = bpack2(dx0, dx1);
        });
    }
    __syncthreads();
    tmm64w1<1,0>(wid, l, Kh, Dh, [&](int m, int n, float v0, float v1){
        g_u1[gbase + m*32 + (n>>1)] = bpack2(-v0, -v1);
    });
}

// ------------------- K5: scans (bf16x2 packed, fp32 state) -------------------
__global__ void k5_scan()
{
    int w  = blockIdx.x*blockDim.x + threadIdx.x;   // 0..2047
    int bh = blockIdx.y;
    uint32_t* g = blockIdx.z ? g_u2 : g_u1;
    const float* mg = g_mg  + bh*NCH;
    const float* dc = g_dec + bh*NCH;
    float m0 = 0.f, m1 = 0.f, u0 = 0.f, u1 = 0.f;
    long base = (long)bh*NCH*2048 + w;
    for (int t = 0; t < NCH; t++){
        float2 s = bunpack2(g[base + (long)t*2048]);
        float a = mg[t], d = 1.f - dc[t];
        m0 = a*m0 + s.x;  m1 = a*m1 + s.y;
        u0 = d*u0 + m0;   u1 = d*u1 + m1;
        g[base + (long)t*2048] = bpack2(u0, u1);
    }
}

// ------------------- K6: retrieve (512 thr) -------------------
__global__ void __launch_bounds__(512)
k6_retrieve(const float* __restrict__ w1, const float* __restrict__ w2,
            const float* __restrict__ gamma)
{
    extern __shared__ __align__(16) char smraw[];
    uint16_t* Qh = (uint16_t*)smraw;     // Q, then O
    uint16_t* Ql = Qh + 64*PH;
    uint16_t* Wh = Ql + 64*PH;
    uint16_t* Wl = Wh + 64*PH;
    uint16_t* Xh = Wl + 64*PH;
    uint16_t* Xl = Xh + 64*PH;

    int nc = blockIdx.x, bh = blockIdx.y;
    int tid = threadIdx.x, wid = tid >> 5, l = tid & 31;
    int h = bh % H, b = bh / H;
    long ubase = ((long)bh*NCH + nc)*2048;
    for (int idx = tid; idx < 4096; idx += 512){
        int r = idx >> 6, c = idx & 63;
        int tok = nc*C + r + (C-1);
        float qv = (tok < T) ? g_q[((long)bh*T + tok)*D + c] : 0.f;
        uint16_t h_, l_;
        bsplit(qv, h_, l_); Qh[r*PH+c] = h_; Ql[r*PH+c] = l_;
    }
    for (int w = tid; w < 2048; w += 512){
        int r = w >> 5, c = (w & 31)*2;
        float2 wv = *(const float2*)&w1[r*64 + c];
        float2 uv = bunpack2(g_u1[ubase + w]);
        uint32_t hw, lw;
        bsplit2(wv.x + uv.x, wv.y + uv.y, hw, lw);
        *(uint32_t*)&Wh[r*PH+c] = hw; *(uint32_t*)&Wl[r*PH+c] = lw;
    }
    __syncthreads();
    tmm64w<0,0>(wid, l, Qh, Ql, Wh, Wl, [&](int m, int n, float v0, float v1){
        uint32_t hw, lw;
        bsplit2(v0*sigm(v0), v1*sigm(v1), hw, lw);
        *(uint32_t*)&Xh[m*PH+n] = hw; *(uint32_t*)&Xl[m*PH+n] = lw;
    });
    __syncthreads();
    for (int w = tid; w < 2048; w += 512){
        int r = w >> 5, c = (w & 31)*2;
        float2 wv = *(const float2*)&w2[r*64 + c];
        float2 uv = bunpack2(g_u2[ubase + w]);
        uint32_t hw, lw;
        bsplit2(wv.x + uv.x, wv.y + uv.y, hw, lw);
        *(uint32_t*)&Wh[r*PH+c] = hw; *(uint32_t*)&Wl[r*PH+c] = lw;
    }
    __syncthreads();
    tmm64w<0,0>(wid, l, Xh, Xl, Wh, Wl, [&](int m, int n, float v0, float v1){
        uint32_t hw, lw;
        bsplit2(v0, v1, hw, lw);
        *(uint32_t*)&Qh[m*PH+n] = hw; *(uint32_t*)&Ql[m*PH+n] = lw;
    });
    __syncthreads();
    int row = tid >> 3, sub = tid & 7;
    float ss = 0.f;
    float ov[8];
    #pragma unroll
    for (int jj = 0; jj < 8; jj++){
        int j = sub + jj*8;
        float v = bjoin(Qh[row*PH+j], Ql[row*PH+j]);
        ov[jj] = v;
        ss += v*v;
    }
    ss += __shfl_xor_sync(0xffffffffu, ss, 1);
    ss += __shfl_xor_sync(0xffffffffu, ss, 2);
    ss += __shfl_xor_sync(0xffffffffu, ss, 4);
    float sc = rsqrtf(ss*(1.f/64) + EPSR);
    int tokq = nc*C + row + (C-1);
    float gate = (tokq < T) ? g_gate[(long)bh*T + tokq] : 0.f;
    float* dst = g_vals + ((long)b*T + nc*C + row)*DIM + h*D;
    #pragma unroll
    for (int jj = 0; jj < 8; jj++){
        int j = sub + jj*8;
        dst[j] = ov[jj]*sc*(gamma[h*D + j] + 1.f)*gate;
    }
}

// ------------------- K0 -------------------
__global__ void k0_zero(float* __restrict__ out)
{
    int i = blockIdx.x*blockDim.x + threadIdx.x;
    const int per = (C-1)*DIM;
    if (i < BB*per){
        int b = i / per, rem = i % per;
        out[(long)b*T*DIM + rem] = 0.f;
    }
}

// ------------------- launch -------------------
extern "C" void kernel_launch(void* const* d_in, const int* in_sizes, int n_in,
                              void* d_out, int out_size)
{
    const float* seq   = (const float*)d_in[0];
    const float* w1    = (const float*)d_in[1];
    const float* w2    = (const float*)d_in[2];
    const float* Wq    = (const float*)d_in[3];
    const float* Wkv   = (const float*)d_in[4];
    const float* Wstep = (const float*)d_in[5];
    const float* Wmom  = (const float*)d_in[6];
    const float* Wdecay= (const float*)d_in[7];
    const float* Wgate = (const float*)d_in[8];
    const float* Wcomb = (const float*)d_in[9];
    const float* gamma = (const float*)d_in[10];
    float* out = (float*)d_out;

    const int SM4 = 8*64*PH*2 + 256;   // 73,984 -> 3 CTAs/SM
    const int SM6 = 6*64*PH*2;         // 55,296
    const int SMG = 2*STGH*2;          // 75,776 -> 2 CTAs/SM

    cudaFuncSetAttribute(k4_grads,    cudaFuncAttributeMaxDynamicSharedMemorySize, SM4);
    cudaFuncSetAttribute(k6_retrieve, cudaFuncAttributeMaxDynamicSharedMemorySize, SM6);
    cudaFuncSetAttribute(kmma,        cudaFuncAttributeMaxDynamicSharedMemorySize, SMG);

    k1_rmsnorm<<<BB*T, 256>>>(seq, Wstep, Wgate);
    k2_chunkgates<<<dim3(NCH, BB), 256>>>(Wmom, Wdecay);
    kmma<<<dim3(12, 256), 512, SMG>>>(Wq, Wkv, nullptr, 0);
    k4_grads<<<dim3(NCH, BH), 512, SM4>>>(w1, w2);
    k5_scan<<<dim3(8, BH, 2), 256>>>();
    k6_retrieve<<<dim3(NCH, BH), 512, SM6>>>(w1, w2, gamma);
    kmma<<<dim3(4, 256), 512, SMG>>>(Wcomb, nullptr, out, 1);
    k0_zero<<<504, 256>>>(out);
}

// round 13
// speedup vs baseline: 1.1120x; 1.1120x over previous
#include <cuda_runtime.h>
#include <cuda_bf16.h>
#include <stdint.h>
#include <math.h>

#define BB   4
#define T    8192
#define DIM  512
#define H    8
#define D    64
#define C    64
#define NCH  128
#define BH   32
#define EPSR 1.1920929e-07f
#define MAXLR 0.01f
#define PH   72

// ------------------- scratch -------------------
__device__ float g_s   [BB*T*DIM];
__device__ float g_q   [BH*T*D];
__device__ float g_k   [BH*T*D];
__device__ float g_v   [BH*T*D];
__device__ float g_lr  [BH*T];
__device__ float g_gate[BH*T];
__device__ float g_mg  [BH*NCH];
__device__ float g_dec [BH*NCH];
__device__ uint32_t g_u1 [(long)BH*NCH*2048];   // bf16x2-packed surprises/updates
__device__ uint32_t g_u2 [(long)BH*NCH*2048];
__device__ float g_vals[BB*T*DIM];

__device__ __forceinline__ float sigm(float x){ return 1.f/(1.f+__expf(-x)); }

__device__ __forceinline__ uint32_t smem_u32(const void* p){
    uint32_t a;
    asm("{ .reg .u64 t; cvta.to.shared.u64 t, %1; cvt.u32.u64 %0, t; }" : "=r"(a) : "l"(p));
    return a;
}
__device__ __forceinline__ void ldm4(uint32_t* r, uint32_t addr){
    asm volatile("ldmatrix.sync.aligned.m8n8.x4.shared.b16 {%0,%1,%2,%3}, [%4];"
                 : "=r"(r[0]),"=r"(r[1]),"=r"(r[2]),"=r"(r[3]) : "r"(addr));
}
__device__ __forceinline__ void ldm4t(uint32_t* r, uint32_t addr){
    asm volatile("ldmatrix.sync.aligned.m8n8.x4.trans.shared.b16 {%0,%1,%2,%3}, [%4];"
                 : "=r"(r[0]),"=r"(r[1]),"=r"(r[2]),"=r"(r[3]) : "r"(addr));
}
__device__ __forceinline__ void mma16816(float* c, const uint32_t* a, uint32_t b0, uint32_t b1){
    asm volatile("mma.sync.aligned.m16n8k16.row.col.f32.bf16.bf16.f32 "
                 "{%0,%1,%2,%3}, {%4,%5,%6,%7}, {%8,%9}, {%0,%1,%2,%3};"
                 : "+f"(c[0]),"+f"(c[1]),"+f"(c[2]),"+f"(c[3])
                 : "r"(a[0]),"r"(a[1]),"r"(a[2]),"r"(a[3]), "r"(b0),"r"(b1));
}
__device__ __forceinline__ void bsplit(float v, uint16_t& hi, uint16_t& lo){
    __nv_bfloat16 h = __float2bfloat16(v);
    __nv_bfloat16 l = __float2bfloat16(v - __bfloat162float(h));
    hi = __bfloat16_as_ushort(h);
    lo = __bfloat16_as_ushort(l);
}
__device__ __forceinline__ float bjoin(uint16_t hi, uint16_t lo){
    return __bfloat162float(__ushort_as_bfloat16(hi)) +
           __bfloat162float(__ushort_as_bfloat16(lo));
}
__device__ __forceinline__ void bsplit2(float v0, float v1, uint32_t& hw, uint32_t& lw){
    uint16_t h0,l0,h1,l1;
    bsplit(v0,h0,l0); bsplit(v1,h1,l1);
    hw = (uint32_t)h0 | ((uint32_t)h1<<16);
    lw = (uint32_t)l0 | ((uint32_t)l1<<16);
}
__device__ __forceinline__ uint32_t bpack2(float v0, float v1){
    return (uint32_t)__bfloat16_as_ushort(__float2bfloat16(v0))
         | ((uint32_t)__bfloat16_as_ushort(__float2bfloat16(v1))<<16);
}
__device__ __forceinline__ float2 bunpack2(uint32_t w){
    return make_float2(__bfloat162float(__ushort_as_bfloat16((uint16_t)(w & 0xffff))),
                       __bfloat162float(__ushort_as_bfloat16((uint16_t)(w >> 16))));
}

// ===== 8-warp 64x64x64 split GEMM (m16 x n32), 3-term =====
template<int AT, int BT, class CB>
__device__ __forceinline__ void tmm64(int wid, int l,
    const uint16_t* Ah_, const uint16_t* Al_,
    const uint16_t* Bh_, const uint16_t* Bl_, CB cb)
{
    int wm = wid & 3, wn = wid >> 2;
    float acc[4][4];
    #pragma unroll
    for (int i = 0; i < 4; i++)
        #pragma unroll
        for (int e = 0; e < 4; e++) acc[i][e] = 0.f;
    uint32_t aAh = smem_u32(Ah_), aAl = smem_u32(Al_);
    uint32_t aBh = smem_u32(Bh_), aBl = smem_u32(Bl_);
    #pragma unroll
    for (int ks = 0; ks < 4; ks++){
        int k0 = ks*16;
        uint32_t ah[4], al[4];
        if (!AT){
            uint32_t ad = (uint32_t)((wm*16 + (l&15))*PH + k0 + ((l>>4)<<3))*2u;
            ldm4(ah, aAh + ad); ldm4(al, aAl + ad);
        } else {
            uint32_t ad = (uint32_t)((k0 + (l&15))*PH + wm*16 + ((l>>4)<<3))*2u;
            uint32_t t[4];
            ldm4t(t, aAh + ad); ah[0]=t[0]; ah[1]=t[2]; ah[2]=t[1]; ah[3]=t[3];
            ldm4t(t, aAl + ad); al[0]=t[0]; al[1]=t[2]; al[2]=t[1]; al[3]=t[3];
        }
        uint32_t bh[2][4], bl[2][4];
        #pragma unroll
        for (int hh = 0; hh < 2; hh++){
            int n0 = wn*32 + hh*16;
            if (!BT){
                uint32_t bd = (uint32_t)((k0 + (l&15))*PH + n0 + ((l>>4)<<3))*2u;
                ldm4t(bh[hh], aBh + bd); ldm4t(bl[hh], aBl + bd);
            } else {
                uint32_t bd = (uint32_t)((n0 + (l&15))*PH + k0 + ((l>>4)<<3))*2u;
                uint32_t t[4];
                ldm4(t, aBh + bd); bh[hh][0]=t[0]; bh[hh][1]=t[2]; bh[hh][2]=t[1]; bh[hh][3]=t[3];
                ldm4(t, aBl + bd); bl[hh][0]=t[0]; bl[hh][1]=t[2]; bl[hh][2]=t[1]; bl[hh][3]=t[3];
            }
        }
        #pragma unroll
        for (int nt = 0; nt < 4; nt++){
            int hh = nt>>1, o = (nt&1)*2;
            mma16816(acc[nt], ah, bh[hh][o], bh[hh][o+1]);
            mma16816(acc[nt], al, bh[hh][o], bh[hh][o+1]);
            mma16816(acc[nt], ah, bl[hh][o], bl[hh][o+1]);
        }
    }
    int m0 = wm*16 + (l>>2);
    #pragma unroll
    for (int nt = 0; nt < 4; nt++){
        int n = wn*32 + nt*8 + ((l&3)<<1);
        cb(m0,   n, acc[nt][0], acc[nt][1]);
        cb(m0+8, n, acc[nt][2], acc[nt][3]);
    }
}

// ===== 16-warp variant (m16 x n16), 3-term =====
template<int AT, int BT, class CB>
__device__ __forceinline__ void tmm64w(int wid, int l,
    const uint16_t* Ah_, const uint16_t* Al_,
    const uint16_t* Bh_, const uint16_t* Bl_, CB cb)
{
    int wm = wid & 3, wn = wid >> 2;
    float acc[2][4];
    #pragma unroll
    for (int i = 0; i < 2; i++)
        #pragma unroll
        for (int e = 0; e < 4; e++) acc[i][e] = 0.f;
    uint32_t aAh = smem_u32(Ah_), aAl = smem_u32(Al_);
    uint32_t aBh = smem_u32(Bh_), aBl = smem_u32(Bl_);
    #pragma unroll
    for (int ks = 0; ks < 4; ks++){
        int k0 = ks*16;
        uint32_t ah[4], al[4];
        if (!AT){
            uint32_t ad = (uint32_t)((wm*16 + (l&15))*PH + k0 + ((l>>4)<<3))*2u;
            ldm4(ah, aAh + ad); ldm4(al, aAl + ad);
        } else {
            uint32_t ad = (uint32_t)((k0 + (l&15))*PH + wm*16 + ((l>>4)<<3))*2u;
            uint32_t t[4];
            ldm4t(t, aAh + ad); ah[0]=t[0]; ah[1]=t[2]; ah[2]=t[1]; ah[3]=t[3];
            ldm4t(t, aAl + ad); al[0]=t[0]; al[1]=t[2]; al[2]=t[1]; al[3]=t[3];
        }
        int n0 = wn*16;
        uint32_t bh[4], bl[4];
        if (!BT){
            uint32_t bd = (uint32_t)((k0 + (l&15))*PH + n0 + ((l>>4)<<3))*2u;
            ldm4t(bh, aBh + bd); ldm4t(bl, aBl + bd);
        } else {
            uint32_t bd = (uint32_t)((n0 + (l&15))*PH + k0 + ((l>>4)<<3))*2u;
            uint32_t t[4];
            ldm4(t, aBh + bd); bh[0]=t[0]; bh[1]=t[2]; bh[2]=t[1]; bh[3]=t[3];
            ldm4(t, aBl + bd); bl[0]=t[0]; bl[1]=t[2]; bl[2]=t[1]; bl[3]=t[3];
        }
        #pragma unroll
        for (int q = 0; q < 2; q++){
            int o = q*2;
            mma16816(acc[q], ah, bh[o], bh[o+1]);
            mma16816(acc[q], al, bh[o], bh[o+1]);
            mma16816(acc[q], ah, bl[o], bl[o+1]);
        }
    }
    int m0 = wm*16 + (l>>2);
    #pragma unroll
    for (int q = 0; q < 2; q++){
        int n = wn*16 + q*8 + ((l&3)<<1);
        cb(m0,   n, acc[q][0], acc[q][1]);
        cb(m0+8, n, acc[q][2], acc[q][3]);
    }
}

// ===== single-term variants (gradient path) =====
template<int AT, int BT, class CB>
__device__ __forceinline__ void tmm64_1(int wid, int l,
    const uint16_t* Ah_, const uint16_t* Bh_, CB cb)
{
    int wm = wid & 3, wn = wid >> 2;
    float acc[4][4];
    #pragma unroll
    for (int i = 0; i < 4; i++)
        #pragma unroll
        for (int e = 0; e < 4; e++) acc[i][e] = 0.f;
    uint32_t aAh = smem_u32(Ah_), aBh = smem_u32(Bh_);
    #pragma unroll
    for (int ks = 0; ks < 4; ks++){
        int k0 = ks*16;
        uint32_t ah[4];
        if (!AT){
            uint32_t ad = (uint32_t)((wm*16 + (l&15))*PH + k0 + ((l>>4)<<3))*2u;
            ldm4(ah, aAh + ad);
        } else {
            uint32_t ad = (uint32_t)((k0 + (l&15))*PH + wm*16 + ((l>>4)<<3))*2u;
            uint32_t t[4];
            ldm4t(t, aAh + ad); ah[0]=t[0]; ah[1]=t[2]; ah[2]=t[1]; ah[3]=t[3];
        }
        #pragma unroll
        for (int hh = 0; hh < 2; hh++){
            int n0 = wn*32 + hh*16;
            uint32_t bh[4];
            if (!BT){
                uint32_t bd = (uint32_t)((k0 + (l&15))*PH + n0 + ((l>>4)<<3))*2u;
                ldm4t(bh, aBh + bd);
            } else {
                uint32_t bd = (uint32_t)((n0 + (l&15))*PH + k0 + ((l>>4)<<3))*2u;
                uint32_t t[4];
                ldm4(t, aBh + bd); bh[0]=t[0]; bh[1]=t[2]; bh[2]=t[1]; bh[3]=t[3];
            }
            mma16816(acc[hh*2],   ah, bh[0], bh[1]);
            mma16816(acc[hh*2+1], ah, bh[2], bh[3]);
        }
    }
    int m0 = wm*16 + (l>>2);
    #pragma unroll
    for (int nt = 0; nt < 4; nt++){
        int n = wn*32 + nt*8 + ((l&3)<<1);
        cb(m0,   n, acc[nt][0], acc[nt][1]);
        cb(m0+8, n, acc[nt][2], acc[nt][3]);
    }
}
template<int AT, int BT, class CB>
__device__ __forceinline__ void tmm64w1(int wid, int l,
    const uint16_t* Ah_, const uint16_t* Bh_, CB cb)
{
    int wm = wid & 3, wn = wid >> 2;
    float acc[2][4];
    #pragma unroll
    for (int i = 0; i < 2; i++)
        #pragma unroll
        for (int e = 0; e < 4; e++) acc[i][e] = 0.f;
    uint32_t aAh = smem_u32(Ah_), aBh = smem_u32(Bh_);
    #pragma unroll
    for (int ks = 0; ks < 4; ks++){
        int k0 = ks*16;
        uint32_t ah[4];
        if (!AT){
            uint32_t ad = (uint32_t)((wm*16 + (l&15))*PH + k0 + ((l>>4)<<3))*2u;
            ldm4(ah, aAh + ad);
        } else {
            uint32_t ad = (uint32_t)((k0 + (l&15))*PH + wm*16 + ((l>>4)<<3))*2u;
            uint32_t t[4];
            ldm4t(t, aAh + ad); ah[0]=t[0]; ah[1]=t[2]; ah[2]=t[1]; ah[3]=t[3];
        }
        int n0 = wn*16;
        uint32_t bh[4];
        if (!BT){
            uint32_t bd = (uint32_t)((k0 + (l&15))*PH + n0 + ((l>>4)<<3))*2u;
            ldm4t(bh, aBh + bd);
        } else {
            uint32_t bd = (uint32_t)((n0 + (l&15))*PH + k0 + ((l>>4)<<3))*2u;
            uint32_t t[4];
            ldm4(t, aBh + bd); bh[0]=t[0]; bh[1]=t[2]; bh[2]=t[1]; bh[3]=t[3];
        }
        mma16816(acc[0], ah, bh[0], bh[1]);
        mma16816(acc[1], ah, bh[2], bh[3]);
    }
    int m0 = wm*16 + (l>>2);
    #pragma unroll
    for (int q = 0; q < 2; q++){
        int n = wn*16 + q*8 + ((l&3)<<1);
        cb(m0,   n, acc[q][0], acc[q][1]);
        cb(m0+8, n, acc[q][2], acc[q][3]);
    }
}

// ------------------- K1 -------------------
__global__ void k1_rmsnorm(const float* __restrict__ seq,
                           const float* __restrict__ Wstep,
                           const float* __restrict__ Wgate)
{
    int tok = blockIdx.x;
    int tid = threadIdx.x;
    __shared__ float s[DIM];
    __shared__ float red[256];
    float x0 = seq[(long)tok*DIM + tid*2];
    float x1 = seq[(long)tok*DIM + tid*2 + 1];
    red[tid] = x0*x0 + x1*x1;
    __syncthreads();
    for (int o = 128; o > 0; o >>= 1){
        if (tid < o) red[tid] += red[tid+o];
        __syncthreads();
    }
    float sc = rsqrtf(red[0]*(1.f/DIM) + EPSR);
    float s0 = x0*sc, s1 = x1*sc;
    s[tid*2] = s0; s[tid*2+1] = s1;
    g_s[(long)tok*DIM + tid*2]     = s0;
    g_s[(long)tok*DIM + tid*2 + 1] = s1;
    __syncthreads();
    int w = tid >> 5, lane = tid & 31;
    float ds = 0.f, dg = 0.f;
    for (int i = lane; i < DIM; i += 32){
        float sv = s[i];
        ds += sv * Wstep[i*H + w];
        dg += sv * Wgate[i*H + w];
    }
    for (int o = 16; o; o >>= 1){
        ds += __shfl_down_sync(0xffffffffu, ds, o);
        dg += __shfl_down_sync(0xffffffffu, dg, o);
    }
    if (lane == 0){
        int b = tok / T, t = tok % T;
        int bh = b*H + w;
        g_lr  [(long)bh*T + t] = sigm(ds) * MAXLR * (2.0f/D);
        g_gate[(long)bh*T + t] = sigm(dg);
    }
}

// ------------------- K2 -------------------
__global__ void k2_chunkgates(const float* __restrict__ Wmom,
                              const float* __restrict__ Wdecay)
{
    int nc = blockIdx.x, b = blockIdx.y;
    int tid = threadIdx.x;
    __shared__ float m[DIM];
    const float* base = g_s + ((long)b*T + nc*C)*DIM;
    float a0 = 0.f, a1 = 0.f;
    for (int r = 0; r < C; r++){
        a0 += base[(long)r*DIM + tid*2];
        a1 += base[(long)r*DIM + tid*2 + 1];
    }
    m[tid*2] = a0*(1.f/C); m[tid*2+1] = a1*(1.f/C);
    __syncthreads();
    int w = tid >> 5, lane = tid & 31;
    float dm = 0.f, dd = 0.f;
    for (int i = lane; i < DIM; i += 32){
        float v = m[i];
        dm += v * Wmom[i*H + w];
        dd += v * Wdecay[i*H + w];
    }
    for (int o = 16; o; o >>= 1){
        dm += __shfl_down_sync(0xffffffffu, dm, o);
        dd += __shfl_down_sync(0xffffffffu, dd, o);
    }
    if (lane == 0){
        int bh = b*H + w;
        g_mg [bh*NCH + nc] = sigm(dm);
        g_dec[bh*NCH + nc] = sigm(dd);
    }
}

// ===================== big GEMMs: bf16 2-split, 256 thr, 2-stage buffer (R9 proven) =====================
#define PA 40
#define PB 136
#define STGH (128*PA + 128*PA + 32*PB + 32*PB)
__global__ void __launch_bounds__(256, 2)
kmma(const float* __restrict__ W0, const float* __restrict__ W1,
     float* __restrict__ outp, int mode)
{
    extern __shared__ __align__(16) uint16_t kms[];

    int tid = threadIdx.x, wid = tid >> 5, l = tid & 31;
    int wm = wid & 1, wn = wid >> 1;
    int row0 = blockIdx.y * 128;
    int col0 = blockIdx.x * 128;

    const float* A; const float* Bp; int ldb, bc0;
    if (mode == 0){
        A = g_s;
        if (col0 < 512){ Bp = W0; ldb = 512;  bc0 = col0; }
        else           { Bp = W1; ldb = 1024; bc0 = col0 - 512; }
    } else {
        A = g_vals; Bp = W0; ldb = 512; bc0 = col0;
    }

    float acc[4][4][4];
    #pragma unroll
    for (int i = 0; i < 4; i++)
        #pragma unroll
        for (int j = 0; j < 4; j++)
            #pragma unroll
            for (int e = 0; e < 4; e++) acc[i][j][e] = 0.f;

    int a_row = tid >> 1, a_cg = (tid & 1)*16;
    int b_row = tid >> 3, b_cg = (tid & 7)*16;

    uint32_t base0 = smem_u32(kms);
    auto AhP = [&](int s){ return kms + s*STGH; };
    auto AlP = [&](int s){ return kms + s*STGH + 128*PA; };
    auto BhP = [&](int s){ return kms + s*STGH + 2*128*PA; };
    auto BlP = [&](int s){ return kms + s*STGH + 2*128*PA + 32*PB; };

    float aR[16];
    {
        const float* ap = A + (long)(row0 + a_row)*512 + a_cg;
        #pragma unroll
        for (int j = 0; j < 4; j++)
            *(float4*)(aR + j*4) = *(const float4*)(ap + j*4);
        uint16_t* Ah = AhP(0); uint16_t* Al = AlP(0);
        #pragma unroll
        for (int j = 0; j < 4; j++){
            uint32_t hw0, lw0, hw1, lw1;
            bsplit2(aR[j*4+0], aR[j*4+1], hw0, lw0);
            bsplit2(aR[j*4+2], aR[j*4+3], hw1, lw1);
            int o = a_row*PA + a_cg + j*4;
            *(uint32_t*)&Ah[o]   = hw0; *(uint32_t*)&Ah[o+2] = hw1;
            *(uint32_t*)&Al[o]   = lw0; *(uint32_t*)&Al[o+2] = lw1;
        }
        const float* bp = Bp + (long)b_row*ldb + bc0 + b_cg;
        uint16_t* Bh = BhP(0); uint16_t* Bl = BlP(0);
        #pragma unroll
        for (int j = 0; j < 4; j++){
            float4 x = *(const float4*)(bp + j*4);
            uint32_t hw0, lw0, hw1, lw1;
            bsplit2(x.x, x.y, hw0, lw0);
            bsplit2(x.z, x.w, hw1, lw1);
            int o = b_row*PB + b_cg + j*4;
            *(uint32_t*)&Bh[o]   = hw0; *(uint32_t*)&Bh[o+2] = hw1;
            *(uint32_t*)&Bl[o]   = lw0; *(uint32_t*)&Bl[o+2] = lw1;
        }
    }
    __syncthreads();

    for (int i = 0; i < 16; i++){
        int cur = i & 1, nxt = cur ^ 1;
        if (i < 15){
            const float* ap = A + (long)(row0 + a_row)*512 + (i+1)*32 + a_cg;
            #pragma unroll
            for (int j = 0; j < 4; j++)
                *(float4*)(aR + j*4) = *(const float4*)(ap + j*4);
        }

        uint32_t aAh = base0 + (uint32_t)(cur*STGH)*2u;
        uint32_t aAl = aAh + 128*PA*2u;
        uint32_t aBh = aAh + 2u*128*PA*2u;
        uint32_t aBl = aBh + 32*PB*2u;

        #pragma unroll
        for (int ks = 0; ks < 2; ks++){
            int k0 = ks*16;
            int arow = wm*64 + (l & 15);
            int acol = k0 + (l >> 4)*8;
            int brow = k0 + (l & 15);
            int bcol = wn*32 + (l >> 4)*8;

            uint32_t ah[4][4], bh2[2][4];
            #pragma unroll
            for (int mt = 0; mt < 4; mt++)
                ldm4(ah[mt], aAh + ((arow + mt*16)*PA + acol)*2);
            #pragma unroll
            for (int bt = 0; bt < 2; bt++)
                ldm4t(bh2[bt], aBh + (brow*PB + bcol + bt*16)*2);
            #pragma unroll
            for (int mt = 0; mt < 4; mt++)
                #pragma unroll
                for (int nt = 0; nt < 4; nt++)
                    mma16816(acc[mt][nt], ah[mt], bh2[nt>>1][(nt&1)?2:0], bh2[nt>>1][(nt&1)?3:1]);
            {
                uint32_t al4[4][4];
                #pragma unroll
                for (int mt = 0; mt < 4; mt++)
                    ldm4(al4[mt], aAl + ((arow + mt*16)*PA + acol)*2);
                #pragma unroll
                for (int mt = 0; mt < 4; mt++)
                    #pragma unroll
                    for (int nt = 0; nt < 4; nt++)
                        mma16816(acc[mt][nt], al4[mt], bh2[nt>>1][(nt&1)?2:0], bh2[nt>>1][(nt&1)?3:1]);
            }
            {
                uint32_t bl2[2][4];
                #pragma unroll
                for (int bt = 0; bt < 2; bt++)
                    ldm4t(bl2[bt], aBl + (brow*PB + bcol + bt*16)*2);
                #pragma unroll
                for (int mt = 0; mt < 4; mt++)
                    #pragma unroll
                    for (int nt = 0; nt < 4; nt++)
                        mma16816(acc[mt][nt], ah[mt], bl2[nt>>1][(nt&1)?2:0], bl2[nt>>1][(nt&1)?3:1]);
            }
        }

        if (i < 15){
            uint16_t* Ah = AhP(nxt); uint16_t* Al = AlP(nxt);
            #pragma unroll
            for (int j = 0; j < 4; j++){
                uint32_t hw0, lw0, hw1, lw1;
                bsplit2(aR[j*4+0], aR[j*4+1], hw0, lw0);
                bsplit2(aR[j*4+2], aR[j*4+3], hw1, lw1);
                int o = a_row*PA + a_cg + j*4;
                *(uint32_t*)&Ah[o]   = hw0; *(uint32_t*)&Ah[o+2] = hw1;
                *(uint32_t*)&Al[o]   = lw0; *(uint32_t*)&Al[o+2] = lw1;
            }
            const float* bp = Bp + (long)((i+1)*32 + b_row)*ldb + bc0 + b_cg;
            uint16_t* Bh = BhP(nxt); uint16_t* Bl = BlP(nxt);
            #pragma unroll
            for (int j = 0; j < 4; j++){
                float4 x = *(const float4*)(bp + j*4);
                uint32_t hw0, lw0, hw1, lw1;
                bsplit2(x.x, x.y, hw0, lw0);
                bsplit2(x.z, x.w, hw1, lw1);
                int o = b_row*PB + b_cg + j*4;
                *(uint32_t*)&Bh[o]   = hw0; *(uint32_t*)&Bh[o+2] = hw1;
                *(uint32_t*)&Bl[o]   = lw0; *(uint32_t*)&Bl[o+2] = lw1;
            }
        }
        __syncthreads();
    }

    int g = l >> 2, tq = l & 3;
    #pragma unroll
    for (int mt = 0; mt < 4; mt++){
        #pragma unroll
        for (int nt = 0; nt < 4; nt++){
            int col = col0 + wn*32 + nt*8 + 2*tq;
            #pragma unroll
            for (int half = 0; half < 2; half++){
                int r = row0 + wm*64 + mt*16 + g + half*8;
                float2 v = make_float2(acc[mt][nt][half*2], acc[mt][nt][half*2+1]);
                if (mode == 0){
                    int mtx = col >> 9, cc = col & 511;
                    int hh = cc >> 6, j0 = cc & 63;
                    float* dst = (mtx == 0) ? g_q : (mtx == 1 ? g_k : g_v);
                    int b_ = r >> 13, tok = r & 8191;
                    *(float2*)(dst + ((long)(b_*H + hh)*T + tok)*D + j0) = v;
                } else {
                    int b_ = r >> 13, jr = r & 8191;
                    if (jr <= T - C)
                        *(float2*)(outp + ((long)b_*T + jr + (C-1))*DIM + col) = v;
                }
            }
        }
    }
}

// ------------------- K4: per-chunk MLP grads (512 thr, 3 CTAs/SM) -------------------
__global__ void __launch_bounds__(512, 3)
k4_grads(const float* __restrict__ w1, const float* __restrict__ w2)
{
    extern __shared__ __align__(16) char smraw[];
    uint16_t* Kh = (uint16_t*)smraw;
    uint16_t* Kl = Kh + 64*PH;
    uint16_t* Wh = Kl + 64*PH;
    uint16_t* Wl = Wh + 64*PH;
    uint16_t* Hh = Wl + 64*PH;
    uint16_t* Hl = Hh + 64*PH;
    uint16_t* Yh = Hl + 64*PH;
    uint16_t* Dh = Yh + 64*PH;
    float* slr = (float*)(Dh + 64*PH);

    int nc = blockIdx.x, bh = blockIdx.y;
    int tid = threadIdx.x, wid = tid >> 5, l = tid & 31;
    long base = ((long)bh*T + nc*C)*D;
    for (int idx = tid; idx < 4096; idx += 512){
        int r = idx >> 6, c = idx & 63;
        uint16_t h_, l_;
        bsplit(g_k[base + idx], h_, l_); Kh[r*PH+c] = h_; Kl[r*PH+c] = l_;
        bsplit(w1[idx],        h_, l_); Wh[r*PH+c] = h_; Wl[r*PH+c] = l_;
    }
    if (tid < 64) slr[tid] = g_lr[(long)bh*T + nc*C + tid];
    __syncthreads();

    tmm64w<0,0>(wid, l, Kh, Kl, Wh, Wl, [&](int m, int n, float v0, float v1){
        *(uint32_t*)&Dh[m*PH+n] = bpack2(v0, v1);
        uint32_t hw, lw;
        bsplit2(v0*sigm(v0), v1*sigm(v1), hw, lw);
        *(uint32_t*)&Hh[m*PH+n] = hw; *(uint32_t*)&Hl[m*PH+n] = lw;
    });
    __syncthreads();
    for (int idx = tid; idx < 4096; idx += 512){
        int r = idx >> 6, c = idx & 63;
        uint16_t h_, l_; bsplit(w2[idx], h_, l_);
        Wh[r*PH+c] = h_; Wl[r*PH+c] = l_;
    }
    __syncthreads();
    tmm64w<0,0>(wid, l, Hh, Hl, Wh, Wl, [&](int m, int n, float y0, float y1){
        float2 vv = *(const float2*)&g_v[base + m*64 + n];
        float lr = slr[m];
        *(uint32_t*)&Yh[m*PH+n] = bpack2(lr*(y0 - vv.x), lr*(y1 - vv.y));
    });
    __syncthreads();
    long gbase = ((long)bh*NCH + nc)*2048;
    if (wid < 8){
        tmm64_1<1,0>(wid, l, Hh, Yh, [&](int m, int n, float v0, float v1){
            g_u2[gbase + m*32 + (n>>1)] = bpack2(-v0, -v1);
        });
    } else {
        tmm64_1<0,1>(wid-8, l, Yh, Wh, [&](int m, int n, float v0, float v1){
            float x0 = __bfloat162float(__ushort_as_bfloat16(Dh[m*PH+n]));
            float x1 = __bfloat162float(__ushort_as_bfloat16(Dh[m*PH+n+1]));
            float sg0 = sigm(x0), sg1 = sigm(x1);
            float dx0 = v0 * sg0 * (1.f + x0*(1.f - sg0));
            float dx1 = v1 * sg1 * (1.f + x1*(1.f - sg1));
            *(uint32_t*)&Dh[m*PH+n] = bpack2(dx0, dx1);
        });
    }
    __syncthreads();
    tmm64w1<1,0>(wid, l, Kh, Dh, [&](int m, int n, float v0, float v1){
        g_u1[gbase + m*32 + (n>>1)] = bpack2(-v0, -v1);
    });
}

// ------------------- K5: scans (bf16x2 packed, fp32 state) -------------------
__global__ void k5_scan()
{
    int w  = blockIdx.x*blockDim.x + threadIdx.x;   // 0..2047
    int bh = blockIdx.y;
    uint32_t* g = blockIdx.z ? g_u2 : g_u1;
    const float* mg = g_mg  + bh*NCH;
    const float* dc = g_dec + bh*NCH;
    float m0 = 0.f, m1 = 0.f, u0 = 0.f, u1 = 0.f;
    long base = (long)bh*NCH*2048 + w;
    for (int t = 0; t < NCH; t++){
        float2 s = bunpack2(g[base + (long)t*2048]);
        float a = mg[t], d = 1.f - dc[t];
        m0 = a*m0 + s.x;  m1 = a*m1 + s.y;
        u0 = d*u0 + m0;   u1 = d*u1 + m1;
        g[base + (long)t*2048] = bpack2(u0, u1);
    }
}

// ------------------- K6: retrieve (512 thr, uncapped regs) -------------------
__global__ void __launch_bounds__(512)
k6_retrieve(const float* __restrict__ w1, const float* __restrict__ w2,
            const float* __restrict__ gamma)
{
    extern __shared__ __align__(16) char smraw[];
    uint16_t* Qh = (uint16_t*)smraw;     // Q, then O
    uint16_t* Ql = Qh + 64*PH;
    uint16_t* Wh = Ql + 64*PH;
    uint16_t* Wl = Wh + 64*PH;
    uint16_t* Xh = Wl + 64*PH;
    uint16_t* Xl = Xh + 64*PH;

    int nc = blockIdx.x, bh = blockIdx.y;
    int tid = threadIdx.x, wid = tid >> 5, l = tid & 31;
    int h = bh % H, b = bh / H;
    long ubase = ((long)bh*NCH + nc)*2048;
    for (int idx = tid; idx < 4096; idx += 512){
        int r = idx >> 6, c = idx & 63;
        int tok = nc*C + r + (C-1);
        float qv = (tok < T) ? g_q[((long)bh*T + tok)*D + c] : 0.f;
        uint16_t h_, l_;
        bsplit(qv, h_, l_); Qh[r*PH+c] = h_; Ql[r*PH+c] = l_;
    }
    for (int w = tid; w < 2048; w += 512){
        int r = w >> 5, c = (w & 31)*2;
        float2 wv = *(const float2*)&w1[r*64 + c];
        float2 uv = bunpack2(g_u1[ubase + w]);
        uint32_t hw, lw;
        bsplit2(wv.x + uv.x, wv.y + uv.y, hw, lw);
        *(uint32_t*)&Wh[r*PH+c] = hw; *(uint32_t*)&Wl[r*PH+c] = lw;
    }
    __syncthreads();
    tmm64w<0,0>(wid, l, Qh, Ql, Wh, Wl, [&](int m, int n, float v0, float v1){
        uint32_t hw, lw;
        bsplit2(v0*sigm(v0), v1*sigm(v1), hw, lw);
        *(uint32_t*)&Xh[m*PH+n] = hw; *(uint32_t*)&Xl[m*PH+n] = lw;
    });
    __syncthreads();
    for (int w = tid; w < 2048; w += 512){
        int r = w >> 5, c = (w & 31)*2;
        float2 wv = *(const float2*)&w2[r*64 + c];
        float2 uv = bunpack2(g_u2[ubase + w]);
        uint32_t hw, lw;
        bsplit2(wv.x + uv.x, wv.y + uv.y, hw, lw);
        *(uint32_t*)&Wh[r*PH+c] = hw; *(uint32_t*)&Wl[r*PH+c] = lw;
    }
    __syncthreads();
    tmm64w<0,0>(wid, l, Xh, Xl, Wh, Wl, [&](int m, int n, float v0, float v1){
        uint32_t hw, lw;
        bsplit2(v0, v1, hw, lw);
        *(uint32_t*)&Qh[m*PH+n] = hw; *(uint32_t*)&Ql[m*PH+n] = lw;
    });
    __syncthreads();
    int row = tid >> 3, sub = tid & 7;
    float ss = 0.f;
    float ov[8];
    #pragma unroll
    for (int jj = 0; jj < 8; jj++){
        int j = sub + jj*8;
        float v = bjoin(Qh[row*PH+j], Ql[row*PH+j]);
        ov[jj] = v;
        ss += v*v;
    }
    ss += __shfl_xor_sync(0xffffffffu, ss, 1);
    ss += __shfl_xor_sync(0xffffffffu, ss, 2);
    ss += __shfl_xor_sync(0xffffffffu, ss, 4);
    float sc = rsqrtf(ss*(1.f/64) + EPSR);
    int tokq = nc*C + row + (C-1);
    float gate = (tokq < T) ? g_gate[(long)bh*T + tokq] : 0.f;
    float* dst = g_vals + ((long)b*T + nc*C + row)*DIM + h*D;
    #pragma unroll
    for (int jj = 0; jj < 8; jj++){
        int j = sub + jj*8;
        dst[j] = ov[jj]*sc*(gamma[h*D + j] + 1.f)*gate;
    }
}

// ------------------- K0 -------------------
__global__ void k0_zero(float* __restrict__ out)
{
    int i = blockIdx.x*blockDim.x + threadIdx.x;
    const int per = (C-1)*DIM;
    if (i < BB*per){
        int b = i / per, rem = i % per;
        out[(long)b*T*DIM + rem] = 0.f;
    }
}

// ------------------- launch -------------------
extern "C" void kernel_launch(void* const* d_in, const int* in_sizes, int n_in,
                              void* d_out, int out_size)
{
    const float* seq   = (const float*)d_in[0];
    const float* w1    = (const float*)d_in[1];
    const float* w2    = (const float*)d_in[2];
    const float* Wq    = (const float*)d_in[3];
    const float* Wkv   = (const float*)d_in[4];
    const float* Wstep = (const float*)d_in[5];
    const float* Wmom  = (const float*)d_in[6];
    const float* Wdecay= (const float*)d_in[7];
    const float* Wgate = (const float*)d_in[8];
    const float* Wcomb = (const float*)d_in[9];
    const float* gamma = (const float*)d_in[10];
    float* out = (float*)d_out;

    const int SM4 = 8*64*PH*2 + 256;   // 73,984 -> 3 CTAs/SM
    const int SM6 = 6*64*PH*2;         // 55,296
    const int SMG = 2*STGH*2;          // 75,776 -> 2 CTAs/SM

    cudaFuncSetAttribute(k4_grads,    cudaFuncAttributeMaxDynamicSharedMemorySize, SM4);
    cudaFuncSetAttribute(k6_retrieve, cudaFuncAttributeMaxDynamicSharedMemorySize, SM6);
    cudaFuncSetAttribute(kmma,        cudaFuncAttributeMaxDynamicSharedMemorySize, SMG);

    k1_rmsnorm<<<BB*T, 256>>>(seq, Wstep, Wgate);
    k2_chunkgates<<<dim3(NCH, BB), 256>>>(Wmom, Wdecay);
    kmma<<<dim3(12, 256), 256, SMG>>>(Wq, Wkv, nullptr, 0);
    k4_grads<<<dim3(NCH, BH), 512, SM4>>>(w1, w2);
    k5_scan<<<dim3(8, BH, 2), 256>>>();
    k6_retrieve<<<dim3(NCH, BH), 512, SM6>>>(w1, w2, gamma);
    kmma<<<dim3(4, 256), 256, SMG>>>(Wcomb, nullptr, out, 1);
    k0_zero<<<504, 256>>>(out);
}

// round 14
// speedup vs baseline: 1.1979x; 1.0772x over previous
#include <cuda_runtime.h>
#include <cuda_bf16.h>
#include <stdint.h>
#include <math.h>

#define BB   4
#define T    8192
#define DIM  512
#define H    8
#define D    64
#define C    64
#define NCH  128
#define BH   32
#define EPSR 1.1920929e-07f
#define MAXLR 0.01f
#define PH   72

// ------------------- scratch -------------------
__device__ float g_s   [BB*T*DIM];
__device__ float g_q   [BH*T*D];
__device__ float g_k   [BH*T*D];
__device__ float g_v   [BH*T*D];
__device__ float g_lr  [BH*T];
__device__ float g_gate[BH*T];
__device__ float g_mg  [BH*NCH];
__device__ float g_dec [BH*NCH];
__device__ uint32_t g_u1 [(long)BH*NCH*2048];
__device__ uint32_t g_u2 [(long)BH*NCH*2048];
__device__ float g_vals[BB*T*DIM];

__device__ __forceinline__ float sigm(float x){ return 1.f/(1.f+__expf(-x)); }

__device__ __forceinline__ uint32_t smem_u32(const void* p){
    uint32_t a;
    asm("{ .reg .u64 t; cvta.to.shared.u64 t, %1; cvt.u32.u64 %0, t; }" : "=r"(a) : "l"(p));
    return a;
}
__device__ __forceinline__ void ldm4(uint32_t* r, uint32_t addr){
    asm volatile("ldmatrix.sync.aligned.m8n8.x4.shared.b16 {%0,%1,%2,%3}, [%4];"
                 : "=r"(r[0]),"=r"(r[1]),"=r"(r[2]),"=r"(r[3]) : "r"(addr));
}
__device__ __forceinline__ void ldm4t(uint32_t* r, uint32_t addr){
    asm volatile("ldmatrix.sync.aligned.m8n8.x4.trans.shared.b16 {%0,%1,%2,%3}, [%4];"
                 : "=r"(r[0]),"=r"(r[1]),"=r"(r[2]),"=r"(r[3]) : "r"(addr));
}
__device__ __forceinline__ void mma16816(float* c, const uint32_t* a, uint32_t b0, uint32_t b1){
    asm volatile("mma.sync.aligned.m16n8k16.row.col.f32.bf16.bf16.f32 "
                 "{%0,%1,%2,%3}, {%4,%5,%6,%7}, {%8,%9}, {%0,%1,%2,%3};"
                 : "+f"(c[0]),"+f"(c[1]),"+f"(c[2]),"+f"(c[3])
                 : "r"(a[0]),"r"(a[1]),"r"(a[2]),"r"(a[3]), "r"(b0),"r"(b1));
}
__device__ __forceinline__ void bsplit(float v, uint16_t& hi, uint16_t& lo){
    __nv_bfloat16 h = __float2bfloat16(v);
    __nv_bfloat16 l = __float2bfloat16(v - __bfloat162float(h));
    hi = __bfloat16_as_ushort(h);
    lo = __bfloat16_as_ushort(l);
}
__device__ __forceinline__ float bjoin(uint16_t hi, uint16_t lo){
    return __bfloat162float(__ushort_as_bfloat16(hi)) +
           __bfloat162float(__ushort_as_bfloat16(lo));
}
__device__ __forceinline__ void bsplit2(float v0, float v1, uint32_t& hw, uint32_t& lw){
    uint16_t h0,l0,h1,l1;
    bsplit(v0,h0,l0); bsplit(v1,h1,l1);
    hw = (uint32_t)h0 | ((uint32_t)h1<<16);
    lw = (uint32_t)l0 | ((uint32_t)l1<<16);
}
__device__ __forceinline__ uint32_t bpack2(float v0, float v1){
    return (uint32_t)__bfloat16_as_ushort(__float2bfloat16(v0))
         | ((uint32_t)__bfloat16_as_ushort(__float2bfloat16(v1))<<16);
}
__device__ __forceinline__ float2 bunpack2(uint32_t w){
    return make_float2(__bfloat162float(__ushort_as_bfloat16((uint16_t)(w & 0xffff))),
                       __bfloat162float(__ushort_as_bfloat16((uint16_t)(w >> 16))));
}

// ===== 8-warp 64x64x64 split GEMM (m16 x n32), 3-term =====
template<int AT, int BT, class CB>
__device__ __forceinline__ void tmm64(int wid, int l,
    const uint16_t* Ah_, const uint16_t* Al_,
    const uint16_t* Bh_, const uint16_t* Bl_, CB cb)
{
    int wm = wid & 3, wn = wid >> 2;
    float acc[4][4];
    #pragma unroll
    for (int i = 0; i < 4; i++)
        #pragma unroll
        for (int e = 0; e < 4; e++) acc[i][e] = 0.f;
    uint32_t aAh = smem_u32(Ah_), aAl = smem_u32(Al_);
    uint32_t aBh = smem_u32(Bh_), aBl = smem_u32(Bl_);
    #pragma unroll
    for (int ks = 0; ks < 4; ks++){
        int k0 = ks*16;
        uint32_t ah[4], al[4];
        if (!AT){
            uint32_t ad = (uint32_t)((wm*16 + (l&15))*PH + k0 + ((l>>4)<<3))*2u;
            ldm4(ah, aAh + ad); ldm4(al, aAl + ad);
        } else {
            uint32_t ad = (uint32_t)((k0 + (l&15))*PH + wm*16 + ((l>>4)<<3))*2u;
            uint32_t t[4];
            ldm4t(t, aAh + ad); ah[0]=t[0]; ah[1]=t[2]; ah[2]=t[1]; ah[3]=t[3];
            ldm4t(t, aAl + ad); al[0]=t[0]; al[1]=t[2]; al[2]=t[1]; al[3]=t[3];
        }
        uint32_t bh[2][4], bl[2][4];
        #pragma unroll
        for (int hh = 0; hh < 2; hh++){
            int n0 = wn*32 + hh*16;
            if (!BT){
                uint32_t bd = (uint32_t)((k0 + (l&15))*PH + n0 + ((l>>4)<<3))*2u;
                ldm4t(bh[hh], aBh + bd); ldm4t(bl[hh], aBl + bd);
            } else {
                uint32_t bd = (uint32_t)((n0 + (l&15))*PH + k0 + ((l>>4)<<3))*2u;
                uint32_t t[4];
                ldm4(t, aBh + bd); bh[hh][0]=t[0]; bh[hh][1]=t[2]; bh[hh][2]=t[1]; bh[hh][3]=t[3];
                ldm4(t, aBl + bd); bl[hh][0]=t[0]; bl[hh][1]=t[2]; bl[hh][2]=t[1]; bl[hh][3]=t[3];
            }
        }
        #pragma unroll
        for (int nt = 0; nt < 4; nt++){
            int hh = nt>>1, o = (nt&1)*2;
            mma16816(acc[nt], ah, bh[hh][o], bh[hh][o+1]);
            mma16816(acc[nt], al, bh[hh][o], bh[hh][o+1]);
            mma16816(acc[nt], ah, bl[hh][o], bl[hh][o+1]);
        }
    }
    int m0 = wm*16 + (l>>2);
    #pragma unroll
    for (int nt = 0; nt < 4; nt++){
        int n = wn*32 + nt*8 + ((l&3)<<1);
        cb(m0,   n, acc[nt][0], acc[nt][1]);
        cb(m0+8, n, acc[nt][2], acc[nt][3]);
    }
}

// ===== 16-warp variant (m16 x n16), 3-term =====
template<int AT, int BT, class CB>
__device__ __forceinline__ void tmm64w(int wid, int l,
    const uint16_t* Ah_, const uint16_t* Al_,
    const uint16_t* Bh_, const uint16_t* Bl_, CB cb)
{
    int wm = wid & 3, wn = wid >> 2;
    float acc[2][4];
    #pragma unroll
    for (int i = 0; i < 2; i++)
        #pragma unroll
        for (int e = 0; e < 4; e++) acc[i][e] = 0.f;
    uint32_t aAh = smem_u32(Ah_), aAl = smem_u32(Al_);
    uint32_t aBh = smem_u32(Bh_), aBl = smem_u32(Bl_);
    #pragma unroll
    for (int ks = 0; ks < 4; ks++){
        int k0 = ks*16;
        uint32_t ah[4], al[4];
        if (!AT){
            uint32_t ad = (uint32_t)((wm*16 + (l&15))*PH + k0 + ((l>>4)<<3))*2u;
            ldm4(ah, aAh + ad); ldm4(al, aAl + ad);
        } else {
            uint32_t ad = (uint32_t)((k0 + (l&15))*PH + wm*16 + ((l>>4)<<3))*2u;
            uint32_t t[4];
            ldm4t(t, aAh + ad); ah[0]=t[0]; ah[1]=t[2]; ah[2]=t[1]; ah[3]=t[3];
            ldm4t(t, aAl + ad); al[0]=t[0]; al[1]=t[2]; al[2]=t[1]; al[3]=t[3];
        }
        int n0 = wn*16;
        uint32_t bh[4], bl[4];
        if (!BT){
            uint32_t bd = (uint32_t)((k0 + (l&15))*PH + n0 + ((l>>4)<<3))*2u;
            ldm4t(bh, aBh + bd); ldm4t(bl, aBl + bd);
        } else {
            uint32_t bd = (uint32_t)((n0 + (l&15))*PH + k0 + ((l>>4)<<3))*2u;
            uint32_t t[4];
            ldm4(t, aBh + bd); bh[0]=t[0]; bh[1]=t[2]; bh[2]=t[1]; bh[3]=t[3];
            ldm4(t, aBl + bd); bl[0]=t[0]; bl[1]=t[2]; bl[2]=t[1]; bl[3]=t[3];
        }
        #pragma unroll
        for (int q = 0; q < 2; q++){
            int o = q*2;
            mma16816(acc[q], ah, bh[o], bh[o+1]);
            mma16816(acc[q], al, bh[o], bh[o+1]);
            mma16816(acc[q], ah, bl[o], bl[o+1]);
        }
    }
    int m0 = wm*16 + (l>>2);
    #pragma unroll
    for (int q = 0; q < 2; q++){
        int n = wn*16 + q*8 + ((l&3)<<1);
        cb(m0,   n, acc[q][0], acc[q][1]);
        cb(m0+8, n, acc[q][2], acc[q][3]);
    }
}

// ===== single-term variants (gradient path) =====
template<int AT, int BT, class CB>
__device__ __forceinline__ void tmm64_1(int wid, int l,
    const uint16_t* Ah_, const uint16_t* Bh_, CB cb)
{
    int wm = wid & 3, wn = wid >> 2;
    float acc[4][4];
    #pragma unroll
    for (int i = 0; i < 4; i++)
        #pragma unroll
        for (int e = 0; e < 4; e++) acc[i][e] = 0.f;
    uint32_t aAh = smem_u32(Ah_), aBh = smem_u32(Bh_);
    #pragma unroll
    for (int ks = 0; ks < 4; ks++){
        int k0 = ks*16;
        uint32_t ah[4];
        if (!AT){
            uint32_t ad = (uint32_t)((wm*16 + (l&15))*PH + k0 + ((l>>4)<<3))*2u;
            ldm4(ah, aAh + ad);
        } else {
            uint32_t ad = (uint32_t)((k0 + (l&15))*PH + wm*16 + ((l>>4)<<3))*2u;
            uint32_t t[4];
            ldm4t(t, aAh + ad); ah[0]=t[0]; ah[1]=t[2]; ah[2]=t[1]; ah[3]=t[3];
        }
        #pragma unroll
        for (int hh = 0; hh < 2; hh++){
            int n0 = wn*32 + hh*16;
            uint32_t bh[4];
            if (!BT){
                uint32_t bd = (uint32_t)((k0 + (l&15))*PH + n0 + ((l>>4)<<3))*2u;
                ldm4t(bh, aBh + bd);
            } else {
                uint32_t bd = (uint32_t)((n0 + (l&15))*PH + k0 + ((l>>4)<<3))*2u;
                uint32_t t[4];
                ldm4(t, aBh + bd); bh[0]=t[0]; bh[1]=t[2]; bh[2]=t[1]; bh[3]=t[3];
            }
            mma16816(acc[hh*2],   ah, bh[0], bh[1]);
            mma16816(acc[hh*2+1], ah, bh[2], bh[3]);
        }
    }
    int m0 = wm*16 + (l>>2);
    #pragma unroll
    for (int nt = 0; nt < 4; nt++){
        int n = wn*32 + nt*8 + ((l&3)<<1);
        cb(m0,   n, acc[nt][0], acc[nt][1]);
        cb(m0+8, n, acc[nt][2], acc[nt][3]);
    }
}
template<int AT, int BT, class CB>
__device__ __forceinline__ void tmm64w1(int wid, int l,
    const uint16_t* Ah_, const uint16_t* Bh_, CB cb)
{
    int wm = wid & 3, wn = wid >> 2;
    float acc[2][4];
    #pragma unroll
    for (int i = 0; i < 2; i++)
        #pragma unroll
        for (int e = 0; e < 4; e++) acc[i][e] = 0.f;
    uint32_t aAh = smem_u32(Ah_), aBh = smem_u32(Bh_);
    #pragma unroll
    for (int ks = 0; ks < 4; ks++){
        int k0 = ks*16;
        uint32_t ah[4];
        if (!AT){
            uint32_t ad = (uint32_t)((wm*16 + (l&15))*PH + k0 + ((l>>4)<<3))*2u;
            ldm4(ah, aAh + ad);
        } else {
            uint32_t ad = (uint32_t)((k0 + (l&15))*PH + wm*16 + ((l>>4)<<3))*2u;
            uint32_t t[4];
            ldm4t(t, aAh + ad); ah[0]=t[0]; ah[1]=t[2]; ah[2]=t[1]; ah[3]=t[3];
        }
        int n0 = wn*16;
        uint32_t bh[4];
        if (!BT){
            uint32_t bd = (uint32_t)((k0 + (l&15))*PH + n0 + ((l>>4)<<3))*2u;
            ldm4t(bh, aBh + bd);
        } else {
            uint32_t bd = (uint32_t)((n0 + (l&15))*PH + k0 + ((l>>4)<<3))*2u;
            uint32_t t[4];
            ldm4(t, aBh + bd); bh[0]=t[0]; bh[1]=t[2]; bh[2]=t[1]; bh[3]=t[3];
        }
        mma16816(acc[0], ah, bh[0], bh[1]);
        mma16816(acc[1], ah, bh[2], bh[3]);
    }
    int m0 = wm*16 + (l>>2);
    #pragma unroll
    for (int q = 0; q < 2; q++){
        int n = wn*16 + q*8 + ((l&3)<<1);
        cb(m0,   n, acc[q][0], acc[q][1]);
        cb(m0+8, n, acc[q][2], acc[q][3]);
    }
}

// ------------------- K1: rmsnorm + lr/gate (warp-shuffle reduction) -------------------
__global__ void k1_rmsnorm(const float* __restrict__ seq,
                           const float* __restrict__ Wstep,
                           const float* __restrict__ Wgate)
{
    int tok = blockIdx.x;
    int tid = threadIdx.x;
    int w = tid >> 5, lane = tid & 31;
    __shared__ float s[DIM];
    __shared__ float red[8];
    float x0 = seq[(long)tok*DIM + tid*2];
    float x1 = seq[(long)tok*DIM + tid*2 + 1];
    float p = x0*x0 + x1*x1;
    #pragma unroll
    for (int o = 16; o; o >>= 1) p += __shfl_xor_sync(0xffffffffu, p, o);
    if (lane == 0) red[w] = p;
    __syncthreads();
    float tot = red[0] + red[1] + red[2] + red[3] + red[4] + red[5] + red[6] + red[7];
    float sc = rsqrtf(tot*(1.f/DIM) + EPSR);
    float s0 = x0*sc, s1 = x1*sc;
    s[tid*2] = s0; s[tid*2+1] = s1;
    g_s[(long)tok*DIM + tid*2]     = s0;
    g_s[(long)tok*DIM + tid*2 + 1] = s1;
    __syncthreads();
    float ds = 0.f, dg = 0.f;
    for (int i = lane; i < DIM; i += 32){
        float sv = s[i];
        ds += sv * Wstep[i*H + w];
        dg += sv * Wgate[i*H + w];
    }
    for (int o = 16; o; o >>= 1){
        ds += __shfl_down_sync(0xffffffffu, ds, o);
        dg += __shfl_down_sync(0xffffffffu, dg, o);
    }
    if (lane == 0){
        int b = tok / T, t = tok % T;
        int bh = b*H + w;
        g_lr  [(long)bh*T + t] = sigm(ds) * MAXLR * (2.0f/D);
        g_gate[(long)bh*T + t] = sigm(dg);
    }
}

// ------------------- K2 -------------------
__global__ void k2_chunkgates(const float* __restrict__ Wmom,
                              const float* __restrict__ Wdecay)
{
    int nc = blockIdx.x, b = blockIdx.y;
    int tid = threadIdx.x;
    __shared__ float m[DIM];
    const float* base = g_s + ((long)b*T + nc*C)*DIM;
    float a0 = 0.f, a1 = 0.f;
    for (int r = 0; r < C; r++){
        a0 += base[(long)r*DIM + tid*2];
        a1 += base[(long)r*DIM + tid*2 + 1];
    }
    m[tid*2] = a0*(1.f/C); m[tid*2+1] = a1*(1.f/C);
    __syncthreads();
    int w = tid >> 5, lane = tid & 31;
    float dm = 0.f, dd = 0.f;
    for (int i = lane; i < DIM; i += 32){
        float v = m[i];
        dm += v * Wmom[i*H + w];
        dd += v * Wdecay[i*H + w];
    }
    for (int o = 16; o; o >>= 1){
        dm += __shfl_down_sync(0xffffffffu, dm, o);
        dd += __shfl_down_sync(0xffffffffu, dd, o);
    }
    if (lane == 0){
        int bh = b*H + w;
        g_mg [bh*NCH + nc] = sigm(dm);
        g_dec[bh*NCH + nc] = sigm(dd);
    }
}

// ===================== big GEMMs: 3-term for q / out, 1-term for k/v =====================
#define PA 40
#define PB 136
#define STGH (128*PA + 128*PA + 32*PB + 32*PB)
__global__ void __launch_bounds__(256, 2)
kmma(const float* __restrict__ W0, const float* __restrict__ W1,
     float* __restrict__ outp, int mode)
{
    extern __shared__ __align__(16) uint16_t kms[];

    int tid = threadIdx.x, wid = tid >> 5, l = tid & 31;
    int wm = wid & 1, wn = wid >> 1;
    int row0 = blockIdx.y * 128;
    int col0 = blockIdx.x * 128;

    const float* A; const float* Bp; int ldb, bc0;
    if (mode == 0){
        A = g_s;
        if (col0 < 512){ Bp = W0; ldb = 512;  bc0 = col0; }
        else           { Bp = W1; ldb = 1024; bc0 = col0 - 512; }
    } else {
        A = g_vals; Bp = W0; ldb = 512; bc0 = col0;
    }
    const bool full = !(mode == 0 && col0 >= 512);   // 1-term bf16 for k/v tiles

    float acc[4][4][4];
    #pragma unroll
    for (int i = 0; i < 4; i++)
        #pragma unroll
        for (int j = 0; j < 4; j++)
            #pragma unroll
            for (int e = 0; e < 4; e++) acc[i][j][e] = 0.f;

    int a_row = tid >> 1, a_cg = (tid & 1)*16;
    int b_row = tid >> 3, b_cg = (tid & 7)*16;

    uint32_t base0 = smem_u32(kms);
    auto AhP = [&](int s){ return kms + s*STGH; };
    auto AlP = [&](int s){ return kms + s*STGH + 128*PA; };
    auto BhP = [&](int s){ return kms + s*STGH + 2*128*PA; };
    auto BlP = [&](int s){ return kms + s*STGH + 2*128*PA + 32*PB; };

    float aR[16];
    {
        const float* ap = A + (long)(row0 + a_row)*512 + a_cg;
        #pragma unroll
        for (int j = 0; j < 4; j++)
            *(float4*)(aR + j*4) = *(const float4*)(ap + j*4);
        uint16_t* Ah = AhP(0); uint16_t* Al = AlP(0);
        #pragma unroll
        for (int j = 0; j < 4; j++){
            uint32_t hw0, lw0, hw1, lw1;
            bsplit2(aR[j*4+0], aR[j*4+1], hw0, lw0);
            bsplit2(aR[j*4+2], aR[j*4+3], hw1, lw1);
            int o = a_row*PA + a_cg + j*4;
            *(uint32_t*)&Ah[o]   = hw0; *(uint32_t*)&Ah[o+2] = hw1;
            if (full){ *(uint32_t*)&Al[o] = lw0; *(uint32_t*)&Al[o+2] = lw1; }
        }
        const float* bp = Bp + (long)b_row*ldb + bc0 + b_cg;
        uint16_t* Bh = BhP(0); uint16_t* Bl = BlP(0);
        #pragma unroll
        for (int j = 0; j < 4; j++){
            float4 x = *(const float4*)(bp + j*4);
            uint32_t hw0, lw0, hw1, lw1;
            bsplit2(x.x, x.y, hw0, lw0);
            bsplit2(x.z, x.w, hw1, lw1);
            int o = b_row*PB + b_cg + j*4;
            *(uint32_t*)&Bh[o]   = hw0; *(uint32_t*)&Bh[o+2] = hw1;
            if (full){ *(uint32_t*)&Bl[o] = lw0; *(uint32_t*)&Bl[o+2] = lw1; }
        }
    }
    __syncthreads();

    for (int i = 0; i < 16; i++){
        int cur = i & 1, nxt = cur ^ 1;
        if (i < 15){
            const float* ap = A + (long)(row0 + a_row)*512 + (i+1)*32 + a_cg;
            #pragma unroll
            for (int j = 0; j < 4; j++)
                *(float4*)(aR + j*4) = *(const float4*)(ap + j*4);
        }

        uint32_t aAh = base0 + (uint32_t)(cur*STGH)*2u;
        uint32_t aAl = aAh + 128*PA*2u;
        uint32_t aBh = aAh + 2u*128*PA*2u;
        uint32_t aBl = aBh + 32*PB*2u;

        #pragma unroll
        for (int ks = 0; ks < 2; ks++){
            int k0 = ks*16;
            int arow = wm*64 + (l & 15);
            int acol = k0 + (l >> 4)*8;
            int brow = k0 + (l & 15);
            int bcol = wn*32 + (l >> 4)*8;

            uint32_t ah[4][4], bh2[2][4];
            #pragma unroll
            for (int mt = 0; mt < 4; mt++)
                ldm4(ah[mt], aAh + ((arow + mt*16)*PA + acol)*2);
            #pragma unroll
            for (int bt = 0; bt < 2; bt++)
                ldm4t(bh2[bt], aBh + (brow*PB + bcol + bt*16)*2);
            #pragma unroll
            for (int mt = 0; mt < 4; mt++)
                #pragma unroll
                for (int nt = 0; nt < 4; nt++)
                    mma16816(acc[mt][nt], ah[mt], bh2[nt>>1][(nt&1)?2:0], bh2[nt>>1][(nt&1)?3:1]);
            if (full){
                uint32_t al4[4][4];
                #pragma unroll
                for (int mt = 0; mt < 4; mt++)
                    ldm4(al4[mt], aAl + ((arow + mt*16)*PA + acol)*2);
                #pragma unroll
                for (int mt = 0; mt < 4; mt++)
                    #pragma unroll
                    for (int nt = 0; nt < 4; nt++)
                        mma16816(acc[mt][nt], al4[mt], bh2[nt>>1][(nt&1)?2:0], bh2[nt>>1][(nt&1)?3:1]);
                uint32_t bl2[2][4];
                #pragma unroll
                for (int bt = 0; bt < 2; bt++)
                    ldm4t(bl2[bt], aBl + (brow*PB + bcol + bt*16)*2);
                #pragma unroll
                for (int mt = 0; mt < 4; mt++)
                    #pragma unroll
                    for (int nt = 0; nt < 4; nt++)
                        mma16816(acc[mt][nt], ah[mt], bl2[nt>>1][(nt&1)?2:0], bl2[nt>>1][(nt&1)?3:1]);
            }
        }

        if (i < 15){
            uint16_t* Ah = AhP(nxt); uint16_t* Al = AlP(nxt);
            #pragma unroll
            for (int j = 0; j < 4; j++){
                uint32_t hw0, lw0, hw1, lw1;
                bsplit2(aR[j*4+0], aR[j*4+1], hw0, lw0);
                bsplit2(aR[j*4+2], aR[j*4+3], hw1, lw1);
                int o = a_row*PA + a_cg + j*4;
                *(uint32_t*)&Ah[o]   = hw0; *(uint32_t*)&Ah[o+2] = hw1;
                if (full){ *(uint32_t*)&Al[o] = lw0; *(uint32_t*)&Al[o+2] = lw1; }
            }
            const float* bp = Bp + (long)((i+1)*32 + b_row)*ldb + bc0 + b_cg;
            uint16_t* Bh = BhP(nxt); uint16_t* Bl = BlP(nxt);
            #pragma unroll
            for (int j = 0; j < 4; j++){
                float4 x = *(const float4*)(bp + j*4);
                uint32_t hw0, lw0, hw1, lw1;
                bsplit2(x.x, x.y, hw0, lw0);
                bsplit2(x.z, x.w, hw1, lw1);
                int o = b_row*PB + b_cg + j*4;
                *(uint32_t*)&Bh[o]   = hw0; *(uint32_t*)&Bh[o+2] = hw1;
                if (full){ *(uint32_t*)&Bl[o] = lw0; *(uint32_t*)&Bl[o+2] = lw1; }
            }
        }
        __syncthreads();
    }

    int g = l >> 2, tq = l & 3;
    #pragma unroll
    for (int mt = 0; mt < 4; mt++){
        #pragma unroll
        for (int nt = 0; nt < 4; nt++){
            int col = col0 + wn*32 + nt*8 + 2*tq;
            #pragma unroll
            for (int half = 0; half < 2; half++){
                int r = row0 + wm*64 + mt*16 + g + half*8;
                float2 v = make_float2(acc[mt][nt][half*2], acc[mt][nt][half*2+1]);
                if (mode == 0){
                    int mtx = col >> 9, cc = col & 511;
                    int hh = cc >> 6, j0 = cc & 63;
                    float* dst = (mtx == 0) ? g_q : (mtx == 1 ? g_k : g_v);
                    int b_ = r >> 13, tok = r & 8191;
                    *(float2*)(dst + ((long)(b_*H + hh)*T + tok)*D + j0) = v;
                } else {
                    int b_ = r >> 13, jr = r & 8191;
                    if (jr <= T - C)
                        *(float2*)(outp + ((long)b_*T + jr + (C-1))*DIM + col) = v;
                }
            }
        }
    }
}

// ------------------- K4: per-chunk MLP grads (512 thr, 3 CTAs/SM) -------------------
__global__ void __launch_bounds__(512, 3)
k4_grads(const float* __restrict__ w1, const float* __restrict__ w2)
{
    extern __shared__ __align__(16) char smraw[];
    uint16_t* Kh = (uint16_t*)smraw;
    uint16_t* Kl = Kh + 64*PH;
    uint16_t* Wh = Kl + 64*PH;
    uint16_t* Wl = Wh + 64*PH;
    uint16_t* Hh = Wl + 64*PH;
    uint16_t* Hl = Hh + 64*PH;
    uint16_t* Yh = Hl + 64*PH;
    uint16_t* Dh = Yh + 64*PH;
    float* slr = (float*)(Dh + 64*PH);

    int nc = blockIdx.x, bh = blockIdx.y;
    int tid = threadIdx.x, wid = tid >> 5, l = tid & 31;
    long base = ((long)bh*T + nc*C)*D;
    for (int idx = tid; idx < 4096; idx += 512){
        int r = idx >> 6, c = idx & 63;
        uint16_t h_, l_;
        bsplit(g_k[base + idx], h_, l_); Kh[r*PH+c] = h_; Kl[r*PH+c] = l_;
        bsplit(w1[idx],        h_, l_); Wh[r*PH+c] = h_; Wl[r*PH+c] = l_;
    }
    if (tid < 64) slr[tid] = g_lr[(long)bh*T + nc*C + tid];
    __syncthreads();

    tmm64w<0,0>(wid, l, Kh, Kl, Wh, Wl, [&](int m, int n, float v0, float v1){
        *(uint32_t*)&Dh[m*PH+n] = bpack2(v0, v1);
        uint32_t hw, lw;
        bsplit2(v0*sigm(v0), v1*sigm(v1), hw, lw);
        *(uint32_t*)&Hh[m*PH+n] = hw; *(uint32_t*)&Hl[m*PH+n] = lw;
    });
    __syncthreads();
    for (int idx = tid; idx < 4096; idx += 512){
        int r = idx >> 6, c = idx & 63;
        uint16_t h_, l_; bsplit(w2[idx], h_, l_);
        Wh[r*PH+c] = h_; Wl[r*PH+c] = l_;
    }
    __syncthreads();
    tmm64w<0,0>(wid, l, Hh, Hl, Wh, Wl, [&](int m, int n, float y0, float y1){
        float2 vv = *(const float2*)&g_v[base + m*64 + n];
        float lr = slr[m];
        *(uint32_t*)&Yh[m*PH+n] = bpack2(lr*(y0 - vv.x), lr*(y1 - vv.y));
    });
    __syncthreads();
    long gbase = ((long)bh*NCH + nc)*2048;
    if (wid < 8){
        tmm64_1<1,0>(wid, l, Hh, Yh, [&](int m, int n, float v0, float v1){
            g_u2[gbase + m*32 + (n>>1)] = bpack2(-v0, -v1);
        });
    } else {
        tmm64_1<0,1>(wid-8, l, Yh, Wh, [&](int m, int n, float v0, float v1){
            float x0 = __bfloat162float(__ushort_as_bfloat16(Dh[m*PH+n]));
            float x1 = __bfloat162float(__ushort_as_bfloat16(Dh[m*PH+n+1]));
            float sg0 = sigm(x0), sg1 = sigm(x1);
            float dx0 = v0 * sg0 * (1.f + x0*(1.f - sg0));
            float dx1 = v1 * sg1 * (1.f + x1*(1.f - sg1));
            *(uint32_t*)&Dh[m*PH+n] = bpack2(dx0, dx1);
        });
    }
    __syncthreads();
    tmm64w1<1,0>(wid, l, Kh, Dh, [&](int m, int n, float v0, float v1){
        g_u1[gbase + m*32 + (n>>1)] = bpack2(-v0, -v1);
    });
}

// ------------------- K5: scans -------------------
__global__ void k5_scan()
{
    int w  = blockIdx.x*blockDim.x + threadIdx.x;
    int bh = blockIdx.y;
    uint32_t* g = blockIdx.z ? g_u2 : g_u1;
    const float* mg = g_mg  + bh*NCH;
    const float* dc = g_dec + bh*NCH;
    float m0 = 0.f, m1 = 0.f, u0 = 0.f, u1 = 0.f;
    long base = (long)bh*NCH*2048 + w;
    for (int t = 0; t < NCH; t++){
        float2 s = bunpack2(g[base + (long)t*2048]);
        float a = mg[t], d = 1.f - dc[t];
        m0 = a*m0 + s.x;  m1 = a*m1 + s.y;
        u0 = d*u0 + m0;   u1 = d*u1 + m1;
        g[base + (long)t*2048] = bpack2(u0, u1);
    }
}

// ------------------- K6: retrieve (512 thr) -------------------
__global__ void __launch_bounds__(512)
k6_retrieve(const float* __restrict__ w1, const float* __restrict__ w2,
            const float* __restrict__ gamma)
{
    extern __shared__ __align__(16) char smraw[];
    uint16_t* Qh = (uint16_t*)smraw;
    uint16_t* Ql = Qh + 64*PH;
    uint16_t* Wh = Ql + 64*PH;
    uint16_t* Wl = Wh + 64*PH;
    uint16_t* Xh = Wl + 64*PH;
    uint16_t* Xl = Xh + 64*PH;

    int nc = blockIdx.x, bh = blockIdx.y;
    int tid = threadIdx.x, wid = tid >> 5, l = tid & 31;
    int h = bh % H, b = bh / H;
    long ubase = ((long)bh*NCH + nc)*2048;
    for (int idx = tid; idx < 4096; idx += 512){
        int r = idx >> 6, c = idx & 63;
        int tok = nc*C + r + (C-1);
        float qv = (tok < T) ? g_q[((long)bh*T + tok)*D + c] : 0.f;
        uint16_t h_, l_;
        bsplit(qv, h_, l_); Qh[r*PH+c] = h_; Ql[r*PH+c] = l_;
    }
    for (int w = tid; w < 2048; w += 512){
        int r = w >> 5, c = (w & 31)*2;
        float2 wv = *(const float2*)&w1[r*64 + c];
        float2 uv = bunpack2(g_u1[ubase + w]);
        uint32_t hw, lw;
        bsplit2(wv.x + uv.x, wv.y + uv.y, hw, lw);
        *(uint32_t*)&Wh[r*PH+c] = hw; *(uint32_t*)&Wl[r*PH+c] = lw;
    }
    __syncthreads();
    tmm64w<0,0>(wid, l, Qh, Ql, Wh, Wl, [&](int m, int n, float v0, float v1){
        uint32_t hw, lw;
        bsplit2(v0*sigm(v0), v1*sigm(v1), hw, lw);
        *(uint32_t*)&Xh[m*PH+n] = hw; *(uint32_t*)&Xl[m*PH+n] = lw;
    });
    __syncthreads();
    for (int w = tid; w < 2048; w += 512){
        int r = w >> 5, c = (w & 31)*2;
        float2 wv = *(const float2*)&w2[r*64 + c];
        float2 uv = bunpack2(g_u2[ubase + w]);
        uint32_t hw, lw;
        bsplit2(wv.x + uv.x, wv.y + uv.y, hw, lw);
        *(uint32_t*)&Wh[r*PH+c] = hw; *(uint32_t*)&Wl[r*PH+c] = lw;
    }
    __syncthreads();
    tmm64w<0,0>(wid, l, Xh, Xl, Wh, Wl, [&](int m, int n, float v0, float v1){
        uint32_t hw, lw;
        bsplit2(v0, v1, hw, lw);
        *(uint32_t*)&Qh[m*PH+n] = hw; *(uint32_t*)&Ql[m*PH+n] = lw;
    });
    __syncthreads();
    int row = tid >> 3, sub = tid & 7;
    float ss = 0.f;
    float ov[8];
    #pragma unroll
    for (int jj = 0; jj < 8; jj++){
        int j = sub + jj*8;
        float v = bjoin(Qh[row*PH+j], Ql[row*PH+j]);
        ov[jj] = v;
        ss += v*v;
    }
    ss += __shfl_xor_sync(0xffffffffu, ss, 1);
    ss += __shfl_xor_sync(0xffffffffu, ss, 2);
    ss += __shfl_xor_sync(0xffffffffu, ss, 4);
    float sc = rsqrtf(ss*(1.f/64) + EPSR);
    int tokq = nc*C + row + (C-1);
    float gate = (tokq < T) ? g_gate[(long)bh*T + tokq] : 0.f;
    float* dst = g_vals + ((long)b*T + nc*C + row)*DIM + h*D;
    #pragma unroll
    for (int jj = 0; jj < 8; jj++){
        int j = sub + jj*8;
        dst[j] = ov[jj]*sc*(gamma[h*D + j] + 1.f)*gate;
    }
}

// ------------------- K0 -------------------
__global__ void k0_zero(float* __restrict__ out)
{
    int i = blockIdx.x*blockDim.x + threadIdx.x;
    const int per = (C-1)*DIM;
    if (i < BB*per){
        int b = i / per, rem = i % per;
        out[(long)b*T*DIM + rem] = 0.f;
    }
}

// ------------------- launch -------------------
extern "C" void kernel_launch(void* const* d_in, const int* in_sizes, int n_in,
                              void* d_out, int out_size)
{
    const float* seq   = (const float*)d_in[0];
    const float* w1    = (const float*)d_in[1];
    const float* w2    = (const float*)d_in[2];
    const float* Wq    = (const float*)d_in[3];
    const float* Wkv   = (const float*)d_in[4];
    const float* Wstep = (const float*)d_in[5];
    const float* Wmom  = (const float*)d_in[6];
    const float* Wdecay= (const float*)d_in[7];
    const float* Wgate = (const float*)d_in[8];
    const float* Wcomb = (const float*)d_in[9];
    const float* gamma = (const float*)d_in[10];
    float* out = (float*)d_out;

    const int SM4 = 8*64*PH*2 + 256;
    const int SM6 = 6*64*PH*2;
    const int SMG = 2*STGH*2;

    cudaFuncSetAttribute(k4_grads,    cudaFuncAttributeMaxDynamicSharedMemorySize, SM4);
    cudaFuncSetAttribute(k6_retrieve, cudaFuncAttributeMaxDynamicSharedMemorySize, SM6);
    cudaFuncSetAttribute(kmma,        cudaFuncAttributeMaxDynamicSharedMemorySize, SMG);

    k1_rmsnorm<<<BB*T, 256>>>(seq, Wstep, Wgate);
    k2_chunkgates<<<dim3(NCH, BB), 256>>>(Wmom, Wdecay);
    kmma<<<dim3(12, 256), 256, SMG>>>(Wq, Wkv, nullptr, 0);
    k4_grads<<<dim3(NCH, BH), 512, SM4>>>(w1, w2);
    k5_scan<<<dim3(8, BH, 2), 256>>>();
    k6_retrieve<<<dim3(NCH, BH), 512, SM6>>>(w1, w2, gamma);
    kmma<<<dim3(4, 256), 256, SMG>>>(Wcomb, nullptr, out, 1);
    k0_zero<<<504, 256>>>(out);
}

// round 16
// speedup vs baseline: 1.2396x; 1.0348x over previous
#include <cuda_runtime.h>
#include <cuda_bf16.h>
#include <stdint.h>
#include <math.h>

#define BB   4
#define T    8192
#define DIM  512
#define H    8
#define D    64
#define C    64
#define NCH  128
#define BH   32
#define EPSR 1.1920929e-07f
#define MAXLR 0.01f
#define PH   72

// ------------------- scratch -------------------
__device__ float g_s   [BB*T*DIM];
__device__ float g_q   [BH*T*D];
__device__ uint32_t g_kp[BH*T*32];   // bf16x2-packed k
__device__ uint32_t g_vp[BH*T*32];   // bf16x2-packed v
__device__ float g_lr  [BH*T];
__device__ float g_gate[BH*T];
__device__ float g_mg  [BH*NCH];
__device__ float g_dec [BH*NCH];
__device__ uint32_t g_u1 [(long)BH*NCH*2048];
__device__ uint32_t g_u2 [(long)BH*NCH*2048];
__device__ float g_vals[BB*T*DIM];

__device__ __forceinline__ float sigm(float x){ return 1.f/(1.f+__expf(-x)); }

__device__ __forceinline__ uint32_t smem_u32(const void* p){
    uint32_t a;
    asm("{ .reg .u64 t; cvta.to.shared.u64 t, %1; cvt.u32.u64 %0, t; }" : "=r"(a) : "l"(p));
    return a;
}
__device__ __forceinline__ void ldm4(uint32_t* r, uint32_t addr){
    asm volatile("ldmatrix.sync.aligned.m8n8.x4.shared.b16 {%0,%1,%2,%3}, [%4];"
                 : "=r"(r[0]),"=r"(r[1]),"=r"(r[2]),"=r"(r[3]) : "r"(addr));
}
__device__ __forceinline__ void ldm4t(uint32_t* r, uint32_t addr){
    asm volatile("ldmatrix.sync.aligned.m8n8.x4.trans.shared.b16 {%0,%1,%2,%3}, [%4];"
                 : "=r"(r[0]),"=r"(r[1]),"=r"(r[2]),"=r"(r[3]) : "r"(addr));
}
__device__ __forceinline__ void mma16816(float* c, const uint32_t* a, uint32_t b0, uint32_t b1){
    asm volatile("mma.sync.aligned.m16n8k16.row.col.f32.bf16.bf16.f32 "
                 "{%0,%1,%2,%3}, {%4,%5,%6,%7}, {%8,%9}, {%0,%1,%2,%3};"
                 : "+f"(c[0]),"+f"(c[1]),"+f"(c[2]),"+f"(c[3])
                 : "r"(a[0]),"r"(a[1]),"r"(a[2]),"r"(a[3]), "r"(b0),"r"(b1));
}
__device__ __forceinline__ void bsplit(float v, uint16_t& hi, uint16_t& lo){
    __nv_bfloat16 h = __float2bfloat16(v);
    __nv_bfloat16 l = __float2bfloat16(v - __bfloat162float(h));
    hi = __bfloat16_as_ushort(h);
    lo = __bfloat16_as_ushort(l);
}
__device__ __forceinline__ float bjoin(uint16_t hi, uint16_t lo){
    return __bfloat162float(__ushort_as_bfloat16(hi)) +
           __bfloat162float(__ushort_as_bfloat16(lo));
}
__device__ __forceinline__ void bsplit2(float v0, float v1, uint32_t& hw, uint32_t& lw){
    uint16_t h0,l0,h1,l1;
    bsplit(v0,h0,l0); bsplit(v1,h1,l1);
    hw = (uint32_t)h0 | ((uint32_t)h1<<16);
    lw = (uint32_t)l0 | ((uint32_t)l1<<16);
}
__device__ __forceinline__ uint32_t bpack2(float v0, float v1){
    return (uint32_t)__bfloat16_as_ushort(__float2bfloat16(v0))
         | ((uint32_t)__bfloat16_as_ushort(__float2bfloat16(v1))<<16);
}
__device__ __forceinline__ float2 bunpack2(uint32_t w){
    return make_float2(__bfloat162float(__ushort_as_bfloat16((uint16_t)(w & 0xffff))),
                       __bfloat162float(__ushort_as_bfloat16((uint16_t)(w >> 16))));
}

// ===== 16-warp variant (m16 x n16), 3-term =====
template<int AT, int BT, class CB>
__device__ __forceinline__ void tmm64w(int wid, int l,
    const uint16_t* Ah_, const uint16_t* Al_,
    const uint16_t* Bh_, const uint16_t* Bl_, CB cb)
{
    int wm = wid & 3, wn = wid >> 2;
    float acc[2][4];
    #pragma unroll
    for (int i = 0; i < 2; i++)
        #pragma unroll
        for (int e = 0; e < 4; e++) acc[i][e] = 0.f;
    uint32_t aAh = smem_u32(Ah_), aAl = smem_u32(Al_);
    uint32_t aBh = smem_u32(Bh_), aBl = smem_u32(Bl_);
    #pragma unroll
    for (int ks = 0; ks < 4; ks++){
        int k0 = ks*16;
        uint32_t ah[4], al[4];
        if (!AT){
            uint32_t ad = (uint32_t)((wm*16 + (l&15))*PH + k0 + ((l>>4)<<3))*2u;
            ldm4(ah, aAh + ad); ldm4(al, aAl + ad);
        } else {
            uint32_t ad = (uint32_t)((k0 + (l&15))*PH + wm*16 + ((l>>4)<<3))*2u;
            uint32_t t[4];
            ldm4t(t, aAh + ad); ah[0]=t[0]; ah[1]=t[2]; ah[2]=t[1]; ah[3]=t[3];
            ldm4t(t, aAl + ad); al[0]=t[0]; al[1]=t[2]; al[2]=t[1]; al[3]=t[3];
        }
        int n0 = wn*16;
        uint32_t bh[4], bl[4];
        if (!BT){
            uint32_t bd = (uint32_t)((k0 + (l&15))*PH + n0 + ((l>>4)<<3))*2u;
            ldm4t(bh, aBh + bd); ldm4t(bl, aBl + bd);
        } else {
            uint32_t bd = (uint32_t)((n0 + (l&15))*PH + k0 + ((l>>4)<<3))*2u;
            uint32_t t[4];
            ldm4(t, aBh + bd); bh[0]=t[0]; bh[1]=t[2]; bh[2]=t[1]; bh[3]=t[3];
            ldm4(t, aBl + bd); bl[0]=t[0]; bl[1]=t[2]; bl[2]=t[1]; bl[3]=t[3];
        }
        #pragma unroll
        for (int q = 0; q < 2; q++){
            int o = q*2;
            mma16816(acc[q], ah, bh[o], bh[o+1]);
            mma16816(acc[q], al, bh[o], bh[o+1]);
            mma16816(acc[q], ah, bl[o], bl[o+1]);
        }
    }
    int m0 = wm*16 + (l>>2);
    #pragma unroll
    for (int q = 0; q < 2; q++){
        int n = wn*16 + q*8 + ((l&3)<<1);
        cb(m0,   n, acc[q][0], acc[q][1]);
        cb(m0+8, n, acc[q][2], acc[q][3]);
    }
}

// ===== single-term variants =====
template<int AT, int BT, class CB>
__device__ __forceinline__ void tmm64_1(int wid, int l,
    const uint16_t* Ah_, const uint16_t* Bh_, CB cb)
{
    int wm = wid & 3, wn = wid >> 2;
    float acc[4][4];
    #pragma unroll
    for (int i = 0; i < 4; i++)
        #pragma unroll
        for (int e = 0; e < 4; e++) acc[i][e] = 0.f;
    uint32_t aAh = smem_u32(Ah_), aBh = smem_u32(Bh_);
    #pragma unroll
    for (int ks = 0; ks < 4; ks++){
        int k0 = ks*16;
        uint32_t ah[4];
        if (!AT){
            uint32_t ad = (uint32_t)((wm*16 + (l&15))*PH + k0 + ((l>>4)<<3))*2u;
            ldm4(ah, aAh + ad);
        } else {
            uint32_t ad = (uint32_t)((k0 + (l&15))*PH + wm*16 + ((l>>4)<<3))*2u;
            uint32_t t[4];
            ldm4t(t, aAh + ad); ah[0]=t[0]; ah[1]=t[2]; ah[2]=t[1]; ah[3]=t[3];
        }
        #pragma unroll
        for (int hh = 0; hh < 2; hh++){
            int n0 = wn*32 + hh*16;
            uint32_t bh[4];
            if (!BT){
                uint32_t bd = (uint32_t)((k0 + (l&15))*PH + n0 + ((l>>4)<<3))*2u;
                ldm4t(bh, aBh + bd);
            } else {
                uint32_t bd = (uint32_t)((n0 + (l&15))*PH + k0 + ((l>>4)<<3))*2u;
                uint32_t t[4];
                ldm4(t, aBh + bd); bh[0]=t[0]; bh[1]=t[2]; bh[2]=t[1]; bh[3]=t[3];
            }
            mma16816(acc[hh*2],   ah, bh[0], bh[1]);
            mma16816(acc[hh*2+1], ah, bh[2], bh[3]);
        }
    }
    int m0 = wm*16 + (l>>2);
    #pragma unroll
    for (int nt = 0; nt < 4; nt++){
        int n = wn*32 + nt*8 + ((l&3)<<1);
        cb(m0,   n, acc[nt][0], acc[nt][1]);
        cb(m0+8, n, acc[nt][2], acc[nt][3]);
    }
}
template<int AT, int BT, class CB>
__device__ __forceinline__ void tmm64w1(int wid, int l,
    const uint16_t* Ah_, const uint16_t* Bh_, CB cb)
{
    int wm = wid & 3, wn = wid >> 2;
    float acc[2][4];
    #pragma unroll
    for (int i = 0; i < 2; i++)
        #pragma unroll
        for (int e = 0; e < 4; e++) acc[i][e] = 0.f;
    uint32_t aAh = smem_u32(Ah_), aBh = smem_u32(Bh_);
    #pragma unroll
    for (int ks = 0; ks < 4; ks++){
        int k0 = ks*16;
        uint32_t ah[4];
        if (!AT){
            uint32_t ad = (uint32_t)((wm*16 + (l&15))*PH + k0 + ((l>>4)<<3))*2u;
            ldm4(ah, aAh + ad);
        } else {
            uint32_t ad = (uint32_t)((k0 + (l&15))*PH + wm*16 + ((l>>4)<<3))*2u;
            uint32_t t[4];
            ldm4t(t, aAh + ad); ah[0]=t[0]; ah[1]=t[2]; ah[2]=t[1]; ah[3]=t[3];
        }
        int n0 = wn*16;
        uint32_t bh[4];
        if (!BT){
            uint32_t bd = (uint32_t)((k0 + (l&15))*PH + n0 + ((l>>4)<<3))*2u;
            ldm4t(bh, aBh + bd);
        } else {
            uint32_t bd = (uint32_t)((n0 + (l&15))*PH + k0 + ((l>>4)<<3))*2u;
            uint32_t t[4];
            ldm4(t, aBh + bd); bh[0]=t[0]; bh[1]=t[2]; bh[2]=t[1]; bh[3]=t[3];
        }
        mma16816(acc[0], ah, bh[0], bh[1]);
        mma16816(acc[1], ah, bh[2], bh[3]);
    }
    int m0 = wm*16 + (l>>2);
    #pragma unroll
    for (int q = 0; q < 2; q++){
        int n = wn*16 + q*8 + ((l&3)<<1);
        cb(m0,   n, acc[q][0], acc[q][1]);
        cb(m0+8, n, acc[q][2], acc[q][3]);
    }
}

// ------------------- K1: rmsnorm + lr/gate -------------------
__global__ void k1_rmsnorm(const float* __restrict__ seq,
                           const float* __restrict__ Wstep,
                           const float* __restrict__ Wgate)
{
    int tok = blockIdx.x;
    int tid = threadIdx.x;
    int w = tid >> 5, lane = tid & 31;
    __shared__ float s[DIM];
    __shared__ float red[8];
    float x0 = seq[(long)tok*DIM + tid*2];
    float x1 = seq[(long)tok*DIM + tid*2 + 1];
    float p = x0*x0 + x1*x1;
    #pragma unroll
    for (int o = 16; o; o >>= 1) p += __shfl_xor_sync(0xffffffffu, p, o);
    if (lane == 0) red[w] = p;
    __syncthreads();
    float tot = red[0] + red[1] + red[2] + red[3] + red[4] + red[5] + red[6] + red[7];
    float sc = rsqrtf(tot*(1.f/DIM) + EPSR);
    float s0 = x0*sc, s1 = x1*sc;
    s[tid*2] = s0; s[tid*2+1] = s1;
    g_s[(long)tok*DIM + tid*2]     = s0;
    g_s[(long)tok*DIM + tid*2 + 1] = s1;
    __syncthreads();
    float ds = 0.f, dg = 0.f;
    for (int i = lane; i < DIM; i += 32){
        float sv = s[i];
        ds += sv * Wstep[i*H + w];
        dg += sv * Wgate[i*H + w];
    }
    for (int o = 16; o; o >>= 1){
        ds += __shfl_down_sync(0xffffffffu, ds, o);
        dg += __shfl_down_sync(0xffffffffu, dg, o);
    }
    if (lane == 0){
        int b = tok / T, t = tok % T;
        int bh = b*H + w;
        g_lr  [(long)bh*T + t] = sigm(ds) * MAXLR * (2.0f/D);
        g_gate[(long)bh*T + t] = sigm(dg);
    }
}

// ------------------- K2 -------------------
__global__ void k2_chunkgates(const float* __restrict__ Wmom,
                              const float* __restrict__ Wdecay)
{
    int nc = blockIdx.x, b = blockIdx.y;
    int tid = threadIdx.x;
    __shared__ float m[DIM];
    const float* base = g_s + ((long)b*T + nc*C)*DIM;
    float a0 = 0.f, a1 = 0.f;
    for (int r = 0; r < C; r++){
        a0 += base[(long)r*DIM + tid*2];
        a1 += base[(long)r*DIM + tid*2 + 1];
    }
    m[tid*2] = a0*(1.f/C); m[tid*2+1] = a1*(1.f/C);
    __syncthreads();
    int w = tid >> 5, lane = tid & 31;
    float dm = 0.f, dd = 0.f;
    for (int i = lane; i < DIM; i += 32){
        float v = m[i];
        dm += v * Wmom[i*H + w];
        dd += v * Wdecay[i*H + w];
    }
    for (int o = 16; o; o >>= 1){
        dm += __shfl_down_sync(0xffffffffu, dm, o);
        dd += __shfl_down_sync(0xffffffffu, dd, o);
    }
    if (lane == 0){
        int bh = b*H + w;
        g_mg [bh*NCH + nc] = sigm(dm);
        g_dec[bh*NCH + nc] = sigm(dd);
    }
}

// ===================== big GEMMs: 3-term q/out, 1-term k/v =====================
#define PA 40
#define PB 136
#define STGH (128*PA + 128*PA + 32*PB + 32*PB)
__global__ void __launch_bounds__(256, 2)
kmma(const float* __restrict__ W0, const float* __restrict__ W1,
     float* __restrict__ outp, int mode)
{
    extern __shared__ __align__(16) uint16_t kms[];

    int tid = threadIdx.x, wid = tid >> 5, l = tid & 31;
    int wm = wid & 1, wn = wid >> 1;
    int row0 = blockIdx.y * 128;
    int col0 = blockIdx.x * 128;

    const float* A; const float* Bp; int ldb, bc0;
    if (mode == 0){
        A = g_s;
        if (col0 < 512){ Bp = W0; ldb = 512;  bc0 = col0; }
        else           { Bp = W1; ldb = 1024; bc0 = col0 - 512; }
    } else {
        A = g_vals; Bp = W0; ldb = 512; bc0 = col0;
    }
    const bool full = !(mode == 0 && col0 >= 512);

    float acc[4][4][4];
    #pragma unroll
    for (int i = 0; i < 4; i++)
        #pragma unroll
        for (int j = 0; j < 4; j++)
            #pragma unroll
            for (int e = 0; e < 4; e++) acc[i][j][e] = 0.f;

    int a_row = tid >> 1, a_cg = (tid & 1)*16;
    int b_row = tid >> 3, b_cg = (tid & 7)*16;

    uint32_t base0 = smem_u32(kms);
    auto AhP = [&](int s){ return kms + s*STGH; };
    auto AlP = [&](int s){ return kms + s*STGH + 128*PA; };
    auto BhP = [&](int s){ return kms + s*STGH + 2*128*PA; };
    auto BlP = [&](int s){ return kms + s*STGH + 2*128*PA + 32*PB; };

    float aR[16];
    {
        const float* ap = A + (long)(row0 + a_row)*512 + a_cg;
        #pragma unroll
        for (int j = 0; j < 4; j++)
            *(float4*)(aR + j*4) = *(const float4*)(ap + j*4);
        uint16_t* Ah = AhP(0); uint16_t* Al = AlP(0);
        #pragma unroll
        for (int j = 0; j < 4; j++){
            uint32_t hw0, lw0, hw1, lw1;
            bsplit2(aR[j*4+0], aR[j*4+1], hw0, lw0);
            bsplit2(aR[j*4+2], aR[j*4+3], hw1, lw1);
            int o = a_row*PA + a_cg + j*4;
            *(uint32_t*)&Ah[o]   = hw0; *(uint32_t*)&Ah[o+2] = hw1;
            if (full){ *(uint32_t*)&Al[o] = lw0; *(uint32_t*)&Al[o+2] = lw1; }
        }
        const float* bp = Bp + (long)b_row*ldb + bc0 + b_cg;
        uint16_t* Bh = BhP(0); uint16_t* Bl = BlP(0);
        #pragma unroll
        for (int j = 0; j < 4; j++){
            float4 x = *(const float4*)(bp + j*4);
            uint32_t hw0, lw0, hw1, lw1;
            bsplit2(x.x, x.y, hw0, lw0);
            bsplit2(x.z, x.w, hw1, lw1);
            int o = b_row*PB + b_cg + j*4;
            *(uint32_t*)&Bh[o]   = hw0; *(uint32_t*)&Bh[o+2] = hw1;
            if (full){ *(uint32_t*)&Bl[o] = lw0; *(uint32_t*)&Bl[o+2] = lw1; }
        }
    }
    __syncthreads();

    for (int i = 0; i < 16; i++){
        int cur = i & 1, nxt = cur ^ 1;
        if (i < 15){
            const float* ap = A + (long)(row0 + a_row)*512 + (i+1)*32 + a_cg;
            #pragma unroll
            for (int j = 0; j < 4; j++)
                *(float4*)(aR + j*4) = *(const float4*)(ap + j*4);
        }

        uint32_t aAh = base0 + (uint32_t)(cur*STGH)*2u;
        uint32_t aAl = aAh + 128*PA*2u;
        uint32_t aBh = aAh + 2u*128*PA*2u;
        uint32_t aBl = aBh + 32*PB*2u;

        #pragma unroll
        for (int ks = 0; ks < 2; ks++){
            int k0 = ks*16;
            int arow = wm*64 + (l & 15);
            int acol = k0 + (l >> 4)*8;
            int brow = k0 + (l & 15);
            int bcol = wn*32 + (l >> 4)*8;

            uint32_t ah[4][4], bh2[2][4];
            #pragma unroll
            for (int mt = 0; mt < 4; mt++)
                ldm4(ah[mt], aAh + ((arow + mt*16)*PA + acol)*2);
            #pragma unroll
            for (int bt = 0; bt < 2; bt++)
                ldm4t(bh2[bt], aBh + (brow*PB + bcol + bt*16)*2);
            #pragma unroll
            for (int mt = 0; mt < 4; mt++)
                #pragma unroll
                for (int nt = 0; nt < 4; nt++)
                    mma16816(acc[mt][nt], ah[mt], bh2[nt>>1][(nt&1)?2:0], bh2[nt>>1][(nt&1)?3:1]);
            if (full){
                uint32_t al4[4][4];
                #pragma unroll
                for (int mt = 0; mt < 4; mt++)
                    ldm4(al4[mt], aAl + ((arow + mt*16)*PA + acol)*2);
                #pragma unroll
                for (int mt = 0; mt < 4; mt++)
                    #pragma unroll
                    for (int nt = 0; nt < 4; nt++)
                        mma16816(acc[mt][nt], al4[mt], bh2[nt>>1][(nt&1)?2:0], bh2[nt>>1][(nt&1)?3:1]);
                uint32_t bl2[2][4];
                #pragma unroll
                for (int bt = 0; bt < 2; bt++)
                    ldm4t(bl2[bt], aBl + (brow*PB + bcol + bt*16)*2);
                #pragma unroll
                for (int mt = 0; mt < 4; mt++)
                    #pragma unroll
                    for (int nt = 0; nt < 4; nt++)
                        mma16816(acc[mt][nt], ah[mt], bl2[nt>>1][(nt&1)?2:0], bl2[nt>>1][(nt&1)?3:1]);
            }
        }

        if (i < 15){
            uint16_t* Ah = AhP(nxt); uint16_t* Al = AlP(nxt);
            #pragma unroll
            for (int j = 0; j < 4; j++){
                uint32_t hw0, lw0, hw1, lw1;
                bsplit2(aR[j*4+0], aR[j*4+1], hw0, lw0);
                bsplit2(aR[j*4+2], aR[j*4+3], hw1, lw1);
                int o = a_row*PA + a_cg + j*4;
                *(uint32_t*)&Ah[o]   = hw0; *(uint32_t*)&Ah[o+2] = hw1;
                if (full){ *(uint32_t*)&Al[o] = lw0; *(uint32_t*)&Al[o+2] = lw1; }
            }
            const float* bp = Bp + (long)((i+1)*32 + b_row)*ldb + bc0 + b_cg;
            uint16_t* Bh = BhP(nxt); uint16_t* Bl = BlP(nxt);
            #pragma unroll
            for (int j = 0; j < 4; j++){
                float4 x = *(const float4*)(bp + j*4);
                uint32_t hw0, lw0, hw1, lw1;
                bsplit2(x.x, x.y, hw0, lw0);
                bsplit2(x.z, x.w, hw1, lw1);
                int o = b_row*PB + b_cg + j*4;
                *(uint32_t*)&Bh[o]   = hw0; *(uint32_t*)&Bh[o+2] = hw1;
                if (full){ *(uint32_t*)&Bl[o] = lw0; *(uint32_t*)&Bl[o+2] = lw1; }
            }
        }
        __syncthreads();
    }

    int g = l >> 2, tq = l & 3;
    #pragma unroll
    for (int mt = 0; mt < 4; mt++){
        #pragma unroll
        for (int nt = 0; nt < 4; nt++){
            int col = col0 + wn*32 + nt*8 + 2*tq;
            #pragma unroll
            for (int half = 0; half < 2; half++){
                int r = row0 + wm*64 + mt*16 + g + half*8;
                float2 v = make_float2(acc[mt][nt][half*2], acc[mt][nt][half*2+1]);
                if (mode == 0){
                    int mtx = col >> 9, cc = col & 511;
                    int hh = cc >> 6, j0 = cc & 63;
                    int b_ = r >> 13, tok = r & 8191;
                    if (mtx == 0){
                        *(float2*)(g_q + ((long)(b_*H + hh)*T + tok)*D + j0) = v;
                    } else {
                        uint32_t* dst = (mtx == 1) ? g_kp : g_vp;
                        dst[((long)(b_*H + hh)*T + tok)*32 + (j0 >> 1)] = bpack2(v.x, v.y);
                    }
                } else {
                    int b_ = r >> 13, jr = r & 8191;
                    if (jr <= T - C)
                        *(float2*)(outp + ((long)b_*T + jr + (C-1))*DIM + col) = v;
                }
            }
        }
    }
}

// ------------------- K4: per-chunk MLP grads — all single-bf16 -------------------
__global__ void __launch_bounds__(512, 3)
k4_grads(const float* __restrict__ w1, const float* __restrict__ w2)
{
    extern __shared__ __align__(16) char smraw[];
    uint16_t* Kh = (uint16_t*)smraw;
    uint16_t* Wh = Kh + 64*PH;
    uint16_t* Hh = Wh + 64*PH;
    uint16_t* Yh = Hh + 64*PH;   // dY
    uint16_t* Dh = Yh + 64*PH;   // X, then dX
    float* slr = (float*)(Dh + 64*PH);

    int nc = blockIdx.x, bh = blockIdx.y;
    int tid = threadIdx.x, wid = tid >> 5, l = tid & 31;
    long base32 = ((long)bh*T + nc*C)*32;
    for (int idx = tid; idx < 2048; idx += 512){
        int r = idx >> 5, c = (idx & 31)*2;
        *(uint32_t*)&Kh[r*PH+c] = g_kp[base32 + idx];     // direct bf16x2 copy
        float2 wv = *(const float2*)&w1[r*64 + c];
        *(uint32_t*)&Wh[r*PH+c] = bpack2(wv.x, wv.y);
    }
    if (tid < 64) slr[tid] = g_lr[(long)bh*T + nc*C + tid];
    __syncthreads();

    // X = K @ W1 (1-term); X -> Dh, H = silu(X) -> Hh
    tmm64w1<0,0>(wid, l, Kh, Wh, [&](int m, int n, float v0, float v1){
        *(uint32_t*)&Dh[m*PH+n] = bpack2(v0, v1);
        *(uint32_t*)&Hh[m*PH+n] = bpack2(v0*sigm(v0), v1*sigm(v1));
    });
    __syncthreads();
    for (int idx = tid; idx < 2048; idx += 512){
        int r = idx >> 5, c = (idx & 31)*2;
        float2 wv = *(const float2*)&w2[r*64 + c];
        *(uint32_t*)&Wh[r*PH+c] = bpack2(wv.x, wv.y);
    }
    __syncthreads();
    // Y = H @ W2 (1-term); dY = lr*(Y - V) -> Yh
    tmm64w1<0,0>(wid, l, Hh, Wh, [&](int m, int n, float y0, float y1){
        float2 vv = bunpack2(g_vp[base32 + m*32 + (n>>1)]);
        float lr = slr[m];
        *(uint32_t*)&Yh[m*PH+n] = bpack2(lr*(y0 - vv.x), lr*(y1 - vv.y));
    });
    __syncthreads();
    long gbase = ((long)bh*NCH + nc)*2048;
    // CONCURRENT: warps 0-7 G2 = H^T@dY ; warps 8-15 dH = dY@W2^T -> dX
    if (wid < 8){
        tmm64_1<1,0>(wid, l, Hh, Yh, [&](int m, int n, float v0, float v1){
            g_u2[gbase + m*32 + (n>>1)] = bpack2(-v0, -v1);
        });
    } else {
        tmm64_1<0,1>(wid-8, l, Yh, Wh, [&](int m, int n, float v0, float v1){
            float x0 = __bfloat162float(__ushort_as_bfloat16(Dh[m*PH+n]));
            float x1 = __bfloat162float(__ushort_as_bfloat16(Dh[m*PH+n+1]));
            float sg0 = sigm(x0), sg1 = sigm(x1);
            float dx0 = v0 * sg0 * (1.f + x0*(1.f - sg0));
            float dx1 = v1 * sg1 * (1.f + x1*(1.f - sg1));
            *(uint32_t*)&Dh[m*PH+n] = bpack2(dx0, dx1);
        });
    }
    __syncthreads();
    // G1 = K^T @ dX (1-term)
    tmm64w1<1,0>(wid, l, Kh, Dh, [&](int m, int n, float v0, float v1){
        g_u1[gbase + m*32 + (n>>1)] = bpack2(-v0, -v1);
    });
}

// ------------------- K5: scans -------------------
__global__ void k5_scan()
{
    int w  = blockIdx.x*blockDim.x + threadIdx.x;
    int bh = blockIdx.y;
    uint32_t* g = blockIdx.z ? g_u2 : g_u1;
    const float* mg = g_mg  + bh*NCH;
    const float* dc = g_dec + bh*NCH;
    float m0 = 0.f, m1 = 0.f, u0 = 0.f, u1 = 0.f;
    long base = (long)bh*NCH*2048 + w;
    for (int t = 0; t < NCH; t++){
        float2 s = bunpack2(g[base + (long)t*2048]);
        float a = mg[t], d = 1.f - dc[t];
        m0 = a*m0 + s.x;  m1 = a*m1 + s.y;
        u0 = d*u0 + m0;   u1 = d*u1 + m1;
        g[base + (long)t*2048] = bpack2(u0, u1);
    }
}

// ------------------- K6: retrieve (512 thr) -------------------
__global__ void __launch_bounds__(512)
k6_retrieve(const float* __restrict__ w1, const float* __restrict__ w2,
            const float* __restrict__ gamma)
{
    extern __shared__ __align__(16) char smraw[];
    uint16_t* Qh = (uint16_t*)smraw;
    uint16_t* Ql = Qh + 64*PH;
    uint16_t* Wh = Ql + 64*PH;
    uint16_t* Wl = Wh + 64*PH;
    uint16_t* Xh = Wl + 64*PH;
    uint16_t* Xl = Xh + 64*PH;

    int nc = blockIdx.x, bh = blockIdx.y;
    int tid = threadIdx.x, wid = tid >> 5, l = tid & 31;
    int h = bh % H, b = bh / H;
    long ubase = ((long)bh*NCH + nc)*2048;
    for (int idx = tid; idx < 4096; idx += 512){
        int r = idx >> 6, c = idx & 63;
        int tok = nc*C + r + (C-1);
        float qv = (tok < T) ? g_q[((long)bh*T + tok)*D + c] : 0.f;
        uint16_t h_, l_;
        bsplit(qv, h_, l_); Qh[r*PH+c] = h_; Ql[r*PH+c] = l_;
    }
    for (int w = tid; w < 2048; w += 512){
        int r = w >> 5, c = (w & 31)*2;
        float2 wv = *(const float2*)&w1[r*64 + c];
        float2 uv = bunpack2(g_u1[ubase + w]);
        uint32_t hw, lw;
        bsplit2(wv.x + uv.x, wv.y + uv.y, hw, lw);
        *(uint32_t*)&Wh[r*PH+c] = hw; *(uint32_t*)&Wl[r*PH+c] = lw;
    }
    __syncthreads();
    tmm64w<0,0>(wid, l, Qh, Ql, Wh, Wl, [&](int m, int n, float v0, float v1){
        uint32_t hw, lw;
        bsplit2(v0*sigm(v0), v1*sigm(v1), hw, lw);
        *(uint32_t*)&Xh[m*PH+n] = hw; *(uint32_t*)&Xl[m*PH+n] = lw;
    });
    __syncthreads();
    for (int w = tid; w < 2048; w += 512){
        int r = w >> 5, c = (w & 31)*2;
        float2 wv = *(const float2*)&w2[r*64 + c];
        float2 uv = bunpack2(g_u2[ubase + w]);
        uint32_t hw, lw;
        bsplit2(wv.x + uv.x, wv.y + uv.y, hw, lw);
        *(uint32_t*)&Wh[r*PH+c] = hw; *(uint32_t*)&Wl[r*PH+c] = lw;
    }
    __syncthreads();
    tmm64w<0,0>(wid, l, Xh, Xl, Wh, Wl, [&](int m, int n, float v0, float v1){
        uint32_t hw, lw;
        bsplit2(v0, v1, hw, lw);
        *(uint32_t*)&Qh[m*PH+n] = hw; *(uint32_t*)&Ql[m*PH+n] = lw;
    });
    __syncthreads();
    int row = tid >> 3, sub = tid & 7;
    float ss = 0.f;
    float ov[8];
    #pragma unroll
    for (int jj = 0; jj < 8; jj++){
        int j = sub + jj*8;
        float v = bjoin(Qh[row*PH+j], Ql[row*PH+j]);
        ov[jj] = v;
        ss += v*v;
    }
    ss += __shfl_xor_sync(0xffffffffu, ss, 1);
    ss += __shfl_xor_sync(0xffffffffu, ss, 2);
    ss += __shfl_xor_sync(0xffffffffu, ss, 4);
    float sc = rsqrtf(ss*(1.f/64) + EPSR);
    int tokq = nc*C + row + (C-1);
    float gate = (tokq < T) ? g_gate[(long)bh*T + tokq] : 0.f;
    float* dst = g_vals + ((long)b*T + nc*C + row)*DIM + h*D;
    #pragma unroll
    for (int jj = 0; jj < 8; jj++){
        int j = sub + jj*8;
        dst[j] = ov[jj]*sc*(gamma[h*D + j] + 1.f)*gate;
    }
}

// ------------------- K0 -------------------
__global__ void k0_zero(float* __restrict__ out)
{
    int i = blockIdx.x*blockDim.x + threadIdx.x;
    const int per = (C-1)*DIM;
    if (i < BB*per){
        int b = i / per, rem = i % per;
        out[(long)b*T*DIM + rem] = 0.f;
    }
}

// ------------------- launch -------------------
extern "C" void kernel_launch(void* const* d_in, const int* in_sizes, int n_in,
                              void* d_out, int out_size)
{
    const float* seq   = (const float*)d_in[0];
    const float* w1    = (const float*)d_in[1];
    const float* w2    = (const float*)d_in[2];
    const float* Wq    = (const float*)d_in[3];
    const float* Wkv   = (const float*)d_in[4];
    const float* Wstep = (const float*)d_in[5];
    const float* Wmom  = (const float*)d_in[6];
    const float* Wdecay= (const float*)d_in[7];
    const float* Wgate = (const float*)d_in[8];
    const float* Wcomb = (const float*)d_in[9];
    const float* gamma = (const float*)d_in[10];
    float* out = (float*)d_out;

    const int SM4 = 5*64*PH*2 + 256;   // 46,336
    const int SM6 = 6*64*PH*2;         // 55,296
    const int SMG = 2*STGH*2;          // 75,776

    cudaFuncSetAttribute(k4_grads,    cudaFuncAttributeMaxDynamicSharedMemorySize, SM4);
    cudaFuncSetAttribute(k6_retrieve, cudaFuncAttributeMaxDynamicSharedMemorySize, SM6);
    cudaFuncSetAttribute(kmma,        cudaFuncAttributeMaxDynamicSharedMemorySize, SMG);

    k1_rmsnorm<<<BB*T, 256>>>(seq, Wstep, Wgate);
    k2_chunkgates<<<dim3(NCH, BB), 256>>>(Wmom, Wdecay);
    kmma<<<dim3(12, 256), 256, SMG>>>(Wq, Wkv, nullptr, 0);
    k4_grads<<<dim3(NCH, BH), 512, SM4>>>(w1, w2);
    k5_scan<<<dim3(8, BH, 2), 256>>>();
    k6_retrieve<<<dim3(NCH, BH), 512, SM6>>>(w1, w2, gamma);
    kmma<<<dim3(4, 256), 256, SMG>>>(Wcomb, nullptr, out, 1);
    k0_zero<<<504, 256>>>(out);
}